// round 1
// baseline (speedup 1.0000x reference)
#include <cuda_runtime.h>
#include <math.h>

#define NN 4096
#define EE 131072
#define HH 256

// ---------------- scratch (static device globals; no allocation) ----------------
__device__ float g_tmp [NN*HH];      // h @ W (pre-aggregation)
__device__ float g_h   [NN*HH];      // running activation
__device__ float g_h3  [NN*HH];      // output of 3rd GCN layer (residual source)
__device__ float g_agg [NN*HH];      // scatter accumulator
__device__ float g_deg [NN];
__device__ float g_dinv[NN];
__device__ float g_qkv [NN*3*HH];
__device__ float g_attn[NN*HH];
__device__ float g_hid [NN*128];

// ---------------- generic tiled fp32 GEMM: C = A[MxK] * B (+bias)(+SRC)(relu) --
// TRANSB: B is [N,K] row-major (torch weight, used as x @ W.T); else B is [K,N].
template<bool TRANSB, bool RELU, bool ADDSRC>
__global__ void __launch_bounds__(256) gemm64(
    const float* __restrict__ A, const float* __restrict__ B,
    const float* __restrict__ bias, const float* __restrict__ SRC,
    float* __restrict__ C, int M, int N, int K)
{
    __shared__ float As[16*64];
    __shared__ float Bs[16*64];
    const int tid = threadIdx.x;
    const int tx  = tid & 15, ty = tid >> 4;
    const int m0  = blockIdx.y * 64, n0 = blockIdx.x * 64;
    const int lm  = tid >> 2;          // 0..63
    const int lk4 = (tid & 3) * 4;     // 0,4,8,12

    float acc[4][4] = {};

    for (int k0 = 0; k0 < K; k0 += 16) {
        float4 av = *(const float4*)(A + (size_t)(m0 + lm) * K + k0 + lk4);
        As[(lk4+0)*64 + lm] = av.x;
        As[(lk4+1)*64 + lm] = av.y;
        As[(lk4+2)*64 + lm] = av.z;
        As[(lk4+3)*64 + lm] = av.w;
        if (TRANSB) {
            float4 bv = *(const float4*)(B + (size_t)(n0 + lm) * K + k0 + lk4);
            Bs[(lk4+0)*64 + lm] = bv.x;
            Bs[(lk4+1)*64 + lm] = bv.y;
            Bs[(lk4+2)*64 + lm] = bv.z;
            Bs[(lk4+3)*64 + lm] = bv.w;
        } else {
            const int bk = tid >> 4;          // 0..15
            const int bn = (tid & 15) * 4;
            float4 bv = *(const float4*)(B + (size_t)(k0 + bk) * N + n0 + bn);
            *(float4*)(Bs + bk*64 + bn) = bv;
        }
        __syncthreads();
        #pragma unroll
        for (int k = 0; k < 16; k++) {
            float4 a4 = *(const float4*)(As + k*64 + ty*4);
            float4 b4 = *(const float4*)(Bs + k*64 + tx*4);
            float af[4] = {a4.x, a4.y, a4.z, a4.w};
            float bf[4] = {b4.x, b4.y, b4.z, b4.w};
            #pragma unroll
            for (int i = 0; i < 4; i++)
                #pragma unroll
                for (int j = 0; j < 4; j++)
                    acc[i][j] = fmaf(af[i], bf[j], acc[i][j]);
        }
        __syncthreads();
    }

    float bb[4] = {0.f, 0.f, 0.f, 0.f};
    if (bias) {
        float4 b4 = *(const float4*)(bias + n0 + tx*4);
        bb[0]=b4.x; bb[1]=b4.y; bb[2]=b4.z; bb[3]=b4.w;
    }
    #pragma unroll
    for (int i = 0; i < 4; i++) {
        const int m = m0 + ty*4 + i;
        float o[4];
        #pragma unroll
        for (int j = 0; j < 4; j++) {
            float v = acc[i][j] + bb[j];
            if (ADDSRC) v += SRC[(size_t)m*N + n0 + tx*4 + j];
            if (RELU)   v  = fmaxf(v, 0.0f);
            o[j] = v;
        }
        *(float4*)(C + (size_t)m*N + n0 + tx*4) = make_float4(o[0],o[1],o[2],o[3]);
    }
}

// ---------------- graph kernels -------------------------------------------------
__global__ void deg_count(const int* __restrict__ dst) {
    int e = blockIdx.x * 256 + threadIdx.x;
    if (e < EE) atomicAdd(&g_deg[dst[e]], 1.0f);
}

__global__ void compute_dinv() {
    int n = blockIdx.x * 256 + threadIdx.x;
    if (n < NN) g_dinv[n] = rsqrtf(g_deg[n] + 1.0f);
}

// one warp per edge: agg[dst] += g_tmp[src] * dinv[src]*dinv[dst]
__global__ void __launch_bounds__(256) edge_agg(const int* __restrict__ src,
                                                const int* __restrict__ dst) {
    int e = blockIdx.x * 8 + (threadIdx.x >> 5);
    int lane = threadIdx.x & 31;
    int s = src[e], d = dst[e];
    float norm = g_dinv[s] * g_dinv[d];
    const float* hs = g_tmp + (size_t)s * HH;
    float*       ad = g_agg + (size_t)d * HH;
    #pragma unroll
    for (int i = 0; i < 8; i++) {
        int c = lane + i * 32;
        atomicAdd(ad + c, hs[c] * norm);
    }
}

template<bool RELU>
__global__ void gcn_combine(const float* __restrict__ bias, float* __restrict__ out) {
    int idx = blockIdx.x * 256 + threadIdx.x;       // over NN*HH
    int n = idx >> 8;
    int c = idx & 255;
    float di = g_dinv[n];
    float v = g_agg[idx] + g_tmp[idx] * (di * di) + bias[c];
    out[idx] = RELU ? fmaxf(v, 0.0f) : v;
}

// ---------------- fp32 flash attention ------------------------------------------
// grid (NN/64, 8 heads), block 256 (16x16). Q/K d-major in smem, V d-major pad 68.
__global__ void __launch_bounds__(256) flash_attn() {
    __shared__ float Qs[32*64];     // [d][row]
    __shared__ float Ks[32*64];     // [d][key]
    __shared__ float Vs[32*68];     // [d][key] padded
    __shared__ float Ps[64*68];     // [row][key] padded (float4-aligned rows)

    const int head = blockIdx.y;
    const int q0   = blockIdx.x * 64;
    const int tid  = threadIdx.x;
    const int tx   = tid & 15, ty = tid >> 4;
    const float scale = 0.17677669529663687f;   // 1/sqrt(32)

    // load Q tile (scaled)
    {
        int r  = tid >> 2;           // 0..63
        int c0 = (tid & 3) * 8;      // 0,8,16,24
        const float* qp = g_qkv + (size_t)(q0 + r) * 768 + head * 32 + c0;
        float4 a = *(const float4*)qp;
        float4 b = *(const float4*)(qp + 4);
        Qs[(c0+0)*64 + r] = a.x * scale;  Qs[(c0+1)*64 + r] = a.y * scale;
        Qs[(c0+2)*64 + r] = a.z * scale;  Qs[(c0+3)*64 + r] = a.w * scale;
        Qs[(c0+4)*64 + r] = b.x * scale;  Qs[(c0+5)*64 + r] = b.y * scale;
        Qs[(c0+6)*64 + r] = b.z * scale;  Qs[(c0+7)*64 + r] = b.w * scale;
    }
    float mreg[4], lreg[4], o0[4], o1[4];
    #pragma unroll
    for (int i = 0; i < 4; i++) { mreg[i] = -1e30f; lreg[i] = 0.f; o0[i] = 0.f; o1[i] = 0.f; }
    __syncthreads();

    for (int kt = 0; kt < NN / 64; kt++) {
        // load K, V tiles
        {
            int r  = tid >> 2;
            int c0 = (tid & 3) * 8;
            const float* kp = g_qkv + (size_t)(kt*64 + r) * 768 + 256 + head * 32 + c0;
            const float* vp = kp + 256;
            float4 ka = *(const float4*)kp,       kb = *(const float4*)(kp + 4);
            float4 va = *(const float4*)vp,       vb = *(const float4*)(vp + 4);
            Ks[(c0+0)*64 + r] = ka.x;  Ks[(c0+1)*64 + r] = ka.y;
            Ks[(c0+2)*64 + r] = ka.z;  Ks[(c0+3)*64 + r] = ka.w;
            Ks[(c0+4)*64 + r] = kb.x;  Ks[(c0+5)*64 + r] = kb.y;
            Ks[(c0+6)*64 + r] = kb.z;  Ks[(c0+7)*64 + r] = kb.w;
            Vs[(c0+0)*68 + r] = va.x;  Vs[(c0+1)*68 + r] = va.y;
            Vs[(c0+2)*68 + r] = va.z;  Vs[(c0+3)*68 + r] = va.w;
            Vs[(c0+4)*68 + r] = vb.x;  Vs[(c0+5)*68 + r] = vb.y;
            Vs[(c0+6)*68 + r] = vb.z;  Vs[(c0+7)*68 + r] = vb.w;
        }
        __syncthreads();

        // S = Q K^T  (4x4 microtile per thread)
        float s[4][4] = {};
        #pragma unroll
        for (int d = 0; d < 32; d++) {
            float4 qa = *(const float4*)(Qs + d*64 + ty*4);
            float4 ka = *(const float4*)(Ks + d*64 + tx*4);
            float qf[4] = {qa.x, qa.y, qa.z, qa.w};
            float kf[4] = {ka.x, ka.y, ka.z, ka.w};
            #pragma unroll
            for (int i = 0; i < 4; i++)
                #pragma unroll
                for (int j = 0; j < 4; j++)
                    s[i][j] = fmaf(qf[i], kf[j], s[i][j]);
        }

        // online softmax per row (16 threads share a row-group via half-warp xor)
        float alpha[4];
        #pragma unroll
        for (int i = 0; i < 4; i++) {
            float tm = fmaxf(fmaxf(s[i][0], s[i][1]), fmaxf(s[i][2], s[i][3]));
            #pragma unroll
            for (int m = 8; m >= 1; m >>= 1) tm = fmaxf(tm, __shfl_xor_sync(0xffffffffu, tm, m));
            float nm = fmaxf(mreg[i], tm);
            float ps = 0.f;
            #pragma unroll
            for (int j = 0; j < 4; j++) { float p = __expf(s[i][j] - nm); s[i][j] = p; ps += p; }
            #pragma unroll
            for (int m = 8; m >= 1; m >>= 1) ps += __shfl_xor_sync(0xffffffffu, ps, m);
            alpha[i] = __expf(mreg[i] - nm);
            lreg[i]  = lreg[i] * alpha[i] + ps;
            mreg[i]  = nm;
            *(float4*)(Ps + (ty*4+i)*68 + tx*4) = make_float4(s[i][0], s[i][1], s[i][2], s[i][3]);
        }
        __syncthreads();

        // O += P @ V   (thread owns rows ty*4..+3, d-cols tx and tx+16)
        #pragma unroll
        for (int i = 0; i < 4; i++) { o0[i] *= alpha[i]; o1[i] *= alpha[i]; }
        #pragma unroll 4
        for (int j4 = 0; j4 < 16; j4++) {
            float4 v0 = *(const float4*)(Vs + tx*68        + j4*4);
            float4 v1 = *(const float4*)(Vs + (tx+16)*68   + j4*4);
            #pragma unroll
            for (int i = 0; i < 4; i++) {
                float4 p = *(const float4*)(Ps + (ty*4+i)*68 + j4*4);
                o0[i] = fmaf(p.x, v0.x, fmaf(p.y, v0.y, fmaf(p.z, v0.z, fmaf(p.w, v0.w, o0[i]))));
                o1[i] = fmaf(p.x, v1.x, fmaf(p.y, v1.y, fmaf(p.z, v1.z, fmaf(p.w, v1.w, o1[i]))));
            }
        }
        __syncthreads();
    }

    #pragma unroll
    for (int i = 0; i < 4; i++) {
        float inv = 1.0f / lreg[i];
        size_t row = (size_t)(q0 + ty*4 + i) * HH + head * 32;
        g_attn[row + tx]      = o0[i] * inv;
        g_attn[row + tx + 16] = o1[i] * inv;
    }
}

// ---------------- tiny output heads ---------------------------------------------
template<int C, bool SOFTMAX>
__global__ void head_kernel(const float* __restrict__ hid, const float* __restrict__ W,
                            const float* __restrict__ b, float* __restrict__ out) {
    __shared__ float sh[128];
    __shared__ float lg[16];
    const int n = blockIdx.x;
    const int t = threadIdx.x;
    sh[t] = hid[(size_t)n * 128 + t];
    __syncthreads();
    if (t < C) {
        float s = b[t];
        #pragma unroll 8
        for (int k = 0; k < 128; k++) s = fmaf(sh[k], W[t*128 + k], s);
        lg[t] = s;
    }
    __syncthreads();
    if (SOFTMAX) {
        if (t == 0) {
            float mx = lg[0];
            #pragma unroll
            for (int c = 1; c < C; c++) mx = fmaxf(mx, lg[c]);
            float e[C]; float sum = 0.f;
            #pragma unroll
            for (int c = 0; c < C; c++) { e[c] = __expf(lg[c] - mx); sum += e[c]; }
            float inv = 1.0f / sum;
            #pragma unroll
            for (int c = 0; c < C; c++) out[(size_t)n*C + c] = e[c] * inv;
        }
    } else {
        if (t < C) out[(size_t)n*C + t] = 1.0f / (1.0f + __expf(-lg[t]));
    }
}

// ---------------- launch ---------------------------------------------------------
extern "C" void kernel_launch(void* const* d_in, const int* in_sizes, int n_in,
                              void* d_out, int out_size)
{
    const float* x     = (const float*)d_in[0];
    const int*   ei    = (const int*)  d_in[1];
    const float* W1    = (const float*)d_in[2];
    const float* b1    = (const float*)d_in[3];
    const float* W2    = (const float*)d_in[4];
    const float* b2    = (const float*)d_in[5];
    const float* W3    = (const float*)d_in[6];
    const float* b3    = (const float*)d_in[7];
    const float* in_w  = (const float*)d_in[8];
    const float* in_b  = (const float*)d_in[9];
    const float* out_w = (const float*)d_in[10];
    const float* out_b = (const float*)d_in[11];
    const float* fp1w  = (const float*)d_in[12];
    const float* fp1b  = (const float*)d_in[13];
    const float* fp2w  = (const float*)d_in[14];
    const float* fp2b  = (const float*)d_in[15];
    const float* pd1w  = (const float*)d_in[16];
    const float* pd1b  = (const float*)d_in[17];
    const float* pd2w  = (const float*)d_in[18];
    const float* pd2b  = (const float*)d_in[19];
    const int* src = ei;
    const int* dst = ei + EE;
    float* outp = (float*)d_out;

    float *tmp, *h, *h3, *agg, *deg, *qkv, *attn, *hid;
    cudaGetSymbolAddress((void**)&tmp,  g_tmp);
    cudaGetSymbolAddress((void**)&h,    g_h);
    cudaGetSymbolAddress((void**)&h3,   g_h3);
    cudaGetSymbolAddress((void**)&agg,  g_agg);
    cudaGetSymbolAddress((void**)&deg,  g_deg);
    cudaGetSymbolAddress((void**)&qkv,  g_qkv);
    cudaGetSymbolAddress((void**)&attn, g_attn);
    cudaGetSymbolAddress((void**)&hid,  g_hid);

    // degrees (shared by all 3 layers)
    cudaMemsetAsync(deg, 0, NN * sizeof(float), 0);
    deg_count<<<EE/256, 256>>>(dst);
    compute_dinv<<<NN/256, 256>>>();

    const dim3 blk(256);
    const dim3 gH(HH/64, NN/64);

    // GCN layer 1: tmp = x @ W1 ; agg ; h = relu(agg + tmp/deg + b1)
    gemm64<false,false,false><<<gH, blk>>>(x, W1, nullptr, nullptr, tmp, NN, HH, 128);
    cudaMemsetAsync(agg, 0, (size_t)NN*HH*sizeof(float), 0);
    edge_agg<<<EE/8, 256>>>(src, dst);
    gcn_combine<true><<<NN*HH/256, 256>>>(b1, h);

    // GCN layer 2
    gemm64<false,false,false><<<gH, blk>>>(h, W2, nullptr, nullptr, tmp, NN, HH, HH);
    cudaMemsetAsync(agg, 0, (size_t)NN*HH*sizeof(float), 0);
    edge_agg<<<EE/8, 256>>>(src, dst);
    gcn_combine<true><<<NN*HH/256, 256>>>(b2, h);

    // GCN layer 3 (no relu) -> h3
    gemm64<false,false,false><<<gH, blk>>>(h, W3, nullptr, nullptr, tmp, NN, HH, HH);
    cudaMemsetAsync(agg, 0, (size_t)NN*HH*sizeof(float), 0);
    edge_agg<<<EE/8, 256>>>(src, dst);
    gcn_combine<false><<<NN*HH/256, 256>>>(b3, h3);

    // MHA: qkv = h3 @ in_w.T + in_b
    gemm64<true,false,false><<<dim3(3*HH/64, NN/64), blk>>>(h3, in_w, in_b, nullptr, qkv, NN, 3*HH, HH);
    flash_attn<<<dim3(NN/64, 8), blk>>>();
    // h = attn @ out_w.T + out_b + h3   (residual)
    gemm64<true,false,true><<<gH, blk>>>(attn, out_w, out_b, h3, h, NN, HH, HH);

    // failure predictor head -> softmax over 3
    gemm64<true,true,false><<<dim3(128/64, NN/64), blk>>>(h, fp1w, fp1b, nullptr, hid, NN, 128, HH);
    head_kernel<3, true><<<NN, 128>>>(hid, fp2w, fp2b, outp);

    // pattern detector head -> sigmoid over 10
    gemm64<true,true,false><<<dim3(128/64, NN/64), blk>>>(h, pd1w, pd1b, nullptr, hid, NN, 128, HH);
    head_kernel<10, false><<<NN, 128>>>(hid, pd2w, pd2b, outp + (size_t)NN*3);
}

// round 3
// speedup vs baseline: 2.1902x; 2.1902x over previous
#include <cuda_runtime.h>
#include <cuda_bf16.h>
#include <cstdint>
#include <math.h>

#define NN 4096
#define EE 131072
#define HH 256

// ---------------- scratch (static device globals; no allocation) ----------------
__device__ float g_tmp [NN*HH];      // h @ W (pre-aggregation)
__device__ float g_h   [NN*HH];      // running activation
__device__ float g_h3  [NN*HH];      // output of 3rd GCN layer (residual source)
__device__ float g_agg [NN*HH];      // scatter accumulator
__device__ float g_deg [NN];
__device__ float g_dinv[NN];
__device__ float g_qkv [NN*3*HH];
__device__ float g_attn[NN*HH];
__device__ float g_hid [NN*128];
__device__ __nv_bfloat16 g_Qb[8*NN*32];   // [h][n][d], pre-scaled by 1/sqrt(32)*log2e
__device__ __nv_bfloat16 g_Kb[8*NN*32];   // [h][n][d]
__device__ __nv_bfloat16 g_Vb[8*32*NN];   // [h][d][n]  (transposed)

// ---------------- generic tiled fp32 GEMM: C = A[MxK] * B (+bias)(+SRC)(relu) --
template<bool TRANSB, bool RELU, bool ADDSRC>
__global__ void __launch_bounds__(256) gemm64(
    const float* __restrict__ A, const float* __restrict__ B,
    const float* __restrict__ bias, const float* __restrict__ SRC,
    float* __restrict__ C, int M, int N, int K)
{
    __shared__ float As[16*64];
    __shared__ float Bs[16*64];
    const int tid = threadIdx.x;
    const int tx  = tid & 15, ty = tid >> 4;
    const int m0  = blockIdx.y * 64, n0 = blockIdx.x * 64;
    const int lm  = tid >> 2;          // 0..63
    const int lk4 = (tid & 3) * 4;     // 0,4,8,12

    float acc[4][4] = {};

    for (int k0 = 0; k0 < K; k0 += 16) {
        float4 av = *(const float4*)(A + (size_t)(m0 + lm) * K + k0 + lk4);
        As[(lk4+0)*64 + lm] = av.x;
        As[(lk4+1)*64 + lm] = av.y;
        As[(lk4+2)*64 + lm] = av.z;
        As[(lk4+3)*64 + lm] = av.w;
        if (TRANSB) {
            float4 bv = *(const float4*)(B + (size_t)(n0 + lm) * K + k0 + lk4);
            Bs[(lk4+0)*64 + lm] = bv.x;
            Bs[(lk4+1)*64 + lm] = bv.y;
            Bs[(lk4+2)*64 + lm] = bv.z;
            Bs[(lk4+3)*64 + lm] = bv.w;
        } else {
            const int bk = tid >> 4;          // 0..15
            const int bn = (tid & 15) * 4;
            float4 bv = *(const float4*)(B + (size_t)(k0 + bk) * N + n0 + bn);
            *(float4*)(Bs + bk*64 + bn) = bv;
        }
        __syncthreads();
        #pragma unroll
        for (int k = 0; k < 16; k++) {
            float4 a4 = *(const float4*)(As + k*64 + ty*4);
            float4 b4 = *(const float4*)(Bs + k*64 + tx*4);
            float af[4] = {a4.x, a4.y, a4.z, a4.w};
            float bf[4] = {b4.x, b4.y, b4.z, b4.w};
            #pragma unroll
            for (int i = 0; i < 4; i++)
                #pragma unroll
                for (int j = 0; j < 4; j++)
                    acc[i][j] = fmaf(af[i], bf[j], acc[i][j]);
        }
        __syncthreads();
    }

    float bb[4] = {0.f, 0.f, 0.f, 0.f};
    if (bias) {
        float4 b4 = *(const float4*)(bias + n0 + tx*4);
        bb[0]=b4.x; bb[1]=b4.y; bb[2]=b4.z; bb[3]=b4.w;
    }
    #pragma unroll
    for (int i = 0; i < 4; i++) {
        const int m = m0 + ty*4 + i;
        float o[4];
        #pragma unroll
        for (int j = 0; j < 4; j++) {
            float v = acc[i][j] + bb[j];
            if (ADDSRC) v += SRC[(size_t)m*N + n0 + tx*4 + j];
            if (RELU)   v  = fmaxf(v, 0.0f);
            o[j] = v;
        }
        *(float4*)(C + (size_t)m*N + n0 + tx*4) = make_float4(o[0],o[1],o[2],o[3]);
    }
}

// ---------------- graph kernels -------------------------------------------------
__global__ void deg_count(const int* __restrict__ dst) {
    int e = blockIdx.x * 256 + threadIdx.x;
    if (e < EE) atomicAdd(&g_deg[dst[e]], 1.0f);
}

__global__ void compute_dinv() {
    int n = blockIdx.x * 256 + threadIdx.x;
    if (n < NN) g_dinv[n] = rsqrtf(g_deg[n] + 1.0f);
}

__global__ void __launch_bounds__(256) edge_agg(const int* __restrict__ src,
                                                const int* __restrict__ dst) {
    int e = blockIdx.x * 8 + (threadIdx.x >> 5);
    int lane = threadIdx.x & 31;
    int s = src[e], d = dst[e];
    float norm = g_dinv[s] * g_dinv[d];
    const float* hs = g_tmp + (size_t)s * HH;
    float*       ad = g_agg + (size_t)d * HH;
    #pragma unroll
    for (int i = 0; i < 8; i++) {
        int c = lane + i * 32;
        atomicAdd(ad + c, hs[c] * norm);
    }
}

template<bool RELU>
__global__ void gcn_combine(const float* __restrict__ bias, float* __restrict__ out) {
    int idx = blockIdx.x * 256 + threadIdx.x;       // over NN*HH
    int n = idx >> 8;
    int c = idx & 255;
    float di = g_dinv[n];
    float v = g_agg[idx] + g_tmp[idx] * (di * di) + bias[c];
    out[idx] = RELU ? fmaxf(v, 0.0f) : v;
}

// ---------------- bf16 conversion for attention ----------------------------------
// Q scaled by 1/sqrt(32)*log2(e) so softmax runs in log2 domain (single EX2).
__global__ void qkv_to_bf16() {
    int idx = blockIdx.x * 256 + threadIdx.x;      // NN*256
    int n = idx >> 8, c = idx & 255;
    int h = c >> 5, d = c & 31;
    const float QSCALE = 0.17677669529663687f * 1.4426950408889634f;
    float q = g_qkv[(size_t)n*768 + c] * QSCALE;
    float k = g_qkv[(size_t)n*768 + 256 + c];
    float v = g_qkv[(size_t)n*768 + 512 + c];
    g_Qb[((size_t)h*NN + n)*32 + d] = __float2bfloat16(q);
    g_Kb[((size_t)h*NN + n)*32 + d] = __float2bfloat16(k);
    g_Vb[((size_t)h*32 + d)*NN + n] = __float2bfloat16(v);
}

// ---------------- bf16 tensor-core flash attention --------------------------------
__device__ __forceinline__ void mma_bf16(float* c, const uint32_t* a, uint32_t b0, uint32_t b1) {
    asm volatile(
        "mma.sync.aligned.m16n8k16.row.col.f32.bf16.bf16.f32 "
        "{%0,%1,%2,%3}, {%4,%5,%6,%7}, {%8,%9}, {%0,%1,%2,%3};\n"
        : "+f"(c[0]), "+f"(c[1]), "+f"(c[2]), "+f"(c[3])
        : "r"(a[0]), "r"(a[1]), "r"(a[2]), "r"(a[3]), "r"(b0), "r"(b1));
}

__device__ __forceinline__ uint32_t pack_bf16(float lo, float hi) {
    __nv_bfloat162 v = __floats2bfloat162_rn(lo, hi);
    return *(uint32_t*)&v;
}

// grid (NN/128, 8 heads), block 256 = 8 warps; each warp owns 16 query rows.
// Key tiles of 64. Ks row stride 36 halves, Vs row stride 72 halves (conflict-free).
__global__ void __launch_bounds__(256) flash_attn_bf16() {
    __shared__ __align__(16) char Ks[64*72];    // [key][36 halves]
    __shared__ __align__(16) char Vs[32*144];   // [d][72 halves]

    const int head = blockIdx.y;
    const int q0   = blockIdx.x * 128;
    const int tid  = threadIdx.x;
    const int w    = tid >> 5, lane = tid & 31;
    const int g    = lane >> 2, t = lane & 3;

    // Q fragments: 2 k-steps (K=32) x 4 regs, loaded once from global
    uint32_t aq[2][4];
    {
        const __nv_bfloat16* qb = g_Qb + ((size_t)head*NN + q0 + w*16) * 32;
        #pragma unroll
        for (int ks = 0; ks < 2; ks++) {
            int c = ks*16 + 2*t;
            aq[ks][0] = *(const uint32_t*)(qb + (size_t)(g  )*32 + c);
            aq[ks][1] = *(const uint32_t*)(qb + (size_t)(g+8)*32 + c);
            aq[ks][2] = *(const uint32_t*)(qb + (size_t)(g  )*32 + c + 8);
            aq[ks][3] = *(const uint32_t*)(qb + (size_t)(g+8)*32 + c + 8);
        }
    }

    float m0 = -1e30f, m1 = -1e30f, l0 = 0.f, l1 = 0.f;
    float o[4][4] = {};    // [nbv][c0..c3]

    const __nv_bfloat16* kg = g_Kb + (size_t)head*NN*32;
    const __nv_bfloat16* vg = g_Vb + (size_t)head*32*NN;

    for (int kt = 0; kt < NN/64; kt++) {
        __syncthreads();
        // stage K tile [64][32] and V tile [32][64]
        {
            int r = tid >> 2, dp = (tid & 3) * 8;
            uint4 kv = *(const uint4*)(kg + (size_t)(kt*64 + r)*32 + dp);
            char* p = Ks + r*72 + dp*2;
            *(uint2*)(p)     = make_uint2(kv.x, kv.y);
            *(uint2*)(p + 8) = make_uint2(kv.z, kv.w);
            int d = tid >> 3, kp = (tid & 7) * 8;
            uint4 vv = *(const uint4*)(vg + (size_t)d*NN + kt*64 + kp);
            *(uint4*)(Vs + d*144 + kp*2) = vv;
        }
        __syncthreads();

        // S = Q K^T : 8 n-blocks of 8 keys
        float s[8][4];
        #pragma unroll
        for (int nb = 0; nb < 8; nb++) {
            s[nb][0] = s[nb][1] = s[nb][2] = s[nb][3] = 0.f;
            const char* kr = Ks + (nb*8 + g)*72;
            uint32_t b0 = *(const uint32_t*)(kr + (2*t)*2);
            uint32_t b1 = *(const uint32_t*)(kr + (2*t+8)*2);
            mma_bf16(s[nb], aq[0], b0, b1);
            b0 = *(const uint32_t*)(kr + (16 + 2*t)*2);
            b1 = *(const uint32_t*)(kr + (16 + 2*t+8)*2);
            mma_bf16(s[nb], aq[1], b0, b1);
        }

        // online softmax (log2 domain), rows g and g+8
        float tm0 = -1e30f, tm1 = -1e30f;
        #pragma unroll
        for (int nb = 0; nb < 8; nb++) {
            tm0 = fmaxf(tm0, fmaxf(s[nb][0], s[nb][1]));
            tm1 = fmaxf(tm1, fmaxf(s[nb][2], s[nb][3]));
        }
        tm0 = fmaxf(tm0, __shfl_xor_sync(0xffffffffu, tm0, 1));
        tm0 = fmaxf(tm0, __shfl_xor_sync(0xffffffffu, tm0, 2));
        tm1 = fmaxf(tm1, __shfl_xor_sync(0xffffffffu, tm1, 1));
        tm1 = fmaxf(tm1, __shfl_xor_sync(0xffffffffu, tm1, 2));
        float nm0 = fmaxf(m0, tm0), nm1 = fmaxf(m1, tm1);
        float al0 = exp2f(m0 - nm0), al1 = exp2f(m1 - nm1);
        m0 = nm0; m1 = nm1;
        float ps0 = 0.f, ps1 = 0.f;
        #pragma unroll
        for (int nb = 0; nb < 8; nb++) {
            s[nb][0] = exp2f(s[nb][0] - nm0);
            s[nb][1] = exp2f(s[nb][1] - nm0);
            s[nb][2] = exp2f(s[nb][2] - nm1);
            s[nb][3] = exp2f(s[nb][3] - nm1);
            ps0 += s[nb][0] + s[nb][1];
            ps1 += s[nb][2] + s[nb][3];
        }
        ps0 += __shfl_xor_sync(0xffffffffu, ps0, 1);
        ps0 += __shfl_xor_sync(0xffffffffu, ps0, 2);
        ps1 += __shfl_xor_sync(0xffffffffu, ps1, 1);
        ps1 += __shfl_xor_sync(0xffffffffu, ps1, 2);
        l0 = l0 * al0 + ps0;
        l1 = l1 * al1 + ps1;

        // rescale O, convert P to bf16 A-fragments (4 k-steps of 16 keys)
        #pragma unroll
        for (int nbv = 0; nbv < 4; nbv++) {
            o[nbv][0] *= al0; o[nbv][1] *= al0;
            o[nbv][2] *= al1; o[nbv][3] *= al1;
        }
        uint32_t ap[4][4];
        #pragma unroll
        for (int s4 = 0; s4 < 4; s4++) {
            ap[s4][0] = pack_bf16(s[2*s4  ][0], s[2*s4  ][1]);
            ap[s4][1] = pack_bf16(s[2*s4  ][2], s[2*s4  ][3]);
            ap[s4][2] = pack_bf16(s[2*s4+1][0], s[2*s4+1][1]);
            ap[s4][3] = pack_bf16(s[2*s4+1][2], s[2*s4+1][3]);
        }

        // O += P @ V
        #pragma unroll
        for (int nbv = 0; nbv < 4; nbv++) {
            const char* vr = Vs + (nbv*8 + g)*144;
            #pragma unroll
            for (int s4 = 0; s4 < 4; s4++) {
                uint32_t b0 = *(const uint32_t*)(vr + (16*s4 + 2*t)*2);
                uint32_t b1 = *(const uint32_t*)(vr + (16*s4 + 2*t + 8)*2);
                mma_bf16(o[nbv], ap[s4], b0, b1);
            }
        }
    }

    // epilogue: normalize, store fp32
    float inv0 = 1.0f / l0, inv1 = 1.0f / l1;
    int row0 = q0 + w*16 + g;
    #pragma unroll
    for (int nbv = 0; nbv < 4; nbv++) {
        int col = head*32 + nbv*8 + 2*t;
        *(float2*)(g_attn + (size_t)row0*HH + col)       = make_float2(o[nbv][0]*inv0, o[nbv][1]*inv0);
        *(float2*)(g_attn + (size_t)(row0+8)*HH + col)   = make_float2(o[nbv][2]*inv1, o[nbv][3]*inv1);
    }
}

// ---------------- tiny output heads ---------------------------------------------
template<int C, bool SOFTMAX>
__global__ void head_kernel(const float* __restrict__ hid, const float* __restrict__ W,
                            const float* __restrict__ b, float* __restrict__ out) {
    __shared__ float sh[128];
    __shared__ float lg[16];
    const int n = blockIdx.x;
    const int t = threadIdx.x;
    sh[t] = hid[(size_t)n * 128 + t];
    __syncthreads();
    if (t < C) {
        float s = b[t];
        #pragma unroll 8
        for (int k = 0; k < 128; k++) s = fmaf(sh[k], W[t*128 + k], s);
        lg[t] = s;
    }
    __syncthreads();
    if (SOFTMAX) {
        if (t == 0) {
            float mx = lg[0];
            #pragma unroll
            for (int c = 1; c < C; c++) mx = fmaxf(mx, lg[c]);
            float e[C]; float sum = 0.f;
            #pragma unroll
            for (int c = 0; c < C; c++) { e[c] = __expf(lg[c] - mx); sum += e[c]; }
            float inv = 1.0f / sum;
            #pragma unroll
            for (int c = 0; c < C; c++) out[(size_t)n*C + c] = e[c] * inv;
        }
    } else {
        if (t < C) out[(size_t)n*C + t] = 1.0f / (1.0f + __expf(-lg[t]));
    }
}

// ---------------- launch ---------------------------------------------------------
extern "C" void kernel_launch(void* const* d_in, const int* in_sizes, int n_in,
                              void* d_out, int out_size)
{
    const float* x     = (const float*)d_in[0];
    const int*   ei    = (const int*)  d_in[1];
    const float* W1    = (const float*)d_in[2];
    const float* b1    = (const float*)d_in[3];
    const float* W2    = (const float*)d_in[4];
    const float* b2    = (const float*)d_in[5];
    const float* W3    = (const float*)d_in[6];
    const float* b3    = (const float*)d_in[7];
    const float* in_w  = (const float*)d_in[8];
    const float* in_b  = (const float*)d_in[9];
    const float* out_w = (const float*)d_in[10];
    const float* out_b = (const float*)d_in[11];
    const float* fp1w  = (const float*)d_in[12];
    const float* fp1b  = (const float*)d_in[13];
    const float* fp2w  = (const float*)d_in[14];
    const float* fp2b  = (const float*)d_in[15];
    const float* pd1w  = (const float*)d_in[16];
    const float* pd1b  = (const float*)d_in[17];
    const float* pd2w  = (const float*)d_in[18];
    const float* pd2b  = (const float*)d_in[19];
    const int* src = ei;
    const int* dst = ei + EE;
    float* outp = (float*)d_out;

    float *tmp, *h, *h3, *agg, *deg, *qkv, *attn, *hid;
    cudaGetSymbolAddress((void**)&tmp,  g_tmp);
    cudaGetSymbolAddress((void**)&h,    g_h);
    cudaGetSymbolAddress((void**)&h3,   g_h3);
    cudaGetSymbolAddress((void**)&agg,  g_agg);
    cudaGetSymbolAddress((void**)&deg,  g_deg);
    cudaGetSymbolAddress((void**)&qkv,  g_qkv);
    cudaGetSymbolAddress((void**)&attn, g_attn);
    cudaGetSymbolAddress((void**)&hid,  g_hid);

    // degrees (shared by all 3 layers)
    cudaMemsetAsync(deg, 0, NN * sizeof(float), 0);
    deg_count<<<EE/256, 256>>>(dst);
    compute_dinv<<<NN/256, 256>>>();

    const dim3 blk(256);
    const dim3 gH(HH/64, NN/64);

    // GCN layer 1
    gemm64<false,false,false><<<gH, blk>>>(x, W1, nullptr, nullptr, tmp, NN, HH, 128);
    cudaMemsetAsync(agg, 0, (size_t)NN*HH*sizeof(float), 0);
    edge_agg<<<EE/8, 256>>>(src, dst);
    gcn_combine<true><<<NN*HH/256, 256>>>(b1, h);

    // GCN layer 2
    gemm64<false,false,false><<<gH, blk>>>(h, W2, nullptr, nullptr, tmp, NN, HH, HH);
    cudaMemsetAsync(agg, 0, (size_t)NN*HH*sizeof(float), 0);
    edge_agg<<<EE/8, 256>>>(src, dst);
    gcn_combine<true><<<NN*HH/256, 256>>>(b2, h);

    // GCN layer 3 (no relu) -> h3
    gemm64<false,false,false><<<gH, blk>>>(h, W3, nullptr, nullptr, tmp, NN, HH, HH);
    cudaMemsetAsync(agg, 0, (size_t)NN*HH*sizeof(float), 0);
    edge_agg<<<EE/8, 256>>>(src, dst);
    gcn_combine<false><<<NN*HH/256, 256>>>(b3, h3);

    // MHA: qkv = h3 @ in_w.T + in_b, then bf16 tensor-core flash attention
    gemm64<true,false,false><<<dim3(3*HH/64, NN/64), blk>>>(h3, in_w, in_b, nullptr, qkv, NN, 3*HH, HH);
    qkv_to_bf16<<<NN, 256>>>();
    flash_attn_bf16<<<dim3(NN/128, 8), blk>>>();
    // h = attn @ out_w.T + out_b + h3   (residual)
    gemm64<true,false,true><<<gH, blk>>>(attn, out_w, out_b, h3, h, NN, HH, HH);

    // failure predictor head -> softmax over 3
    gemm64<true,true,false><<<dim3(128/64, NN/64), blk>>>(h, fp1w, fp1b, nullptr, hid, NN, 128, HH);
    head_kernel<3, true><<<NN, 128>>>(hid, fp2w, fp2b, outp);

    // pattern detector head -> sigmoid over 10
    gemm64<true,true,false><<<dim3(128/64, NN/64), blk>>>(h, pd1w, pd1b, nullptr, hid, NN, 128, HH);
    head_kernel<10, false><<<NN, 128>>>(hid, pd2w, pd2b, outp + (size_t)NN*3);
}

// round 4
// speedup vs baseline: 2.9449x; 1.3446x over previous
#include <cuda_runtime.h>
#include <cuda_bf16.h>
#include <cstdint>
#include <math.h>

#define NN 4096
#define EE 131072
#define HH 256

// ---------------- scratch (static device globals; no allocation) ----------------
__device__ float g_tmp [NN*HH];      // h @ W (pre-aggregation)
__device__ float g_h   [NN*HH];      // running activation
__device__ float g_h3  [NN*HH];      // output of 3rd GCN layer (residual source)
__device__ float g_deg [NN];
__device__ float g_dinv[NN];
__device__ float g_qkv [NN*3*HH];
__device__ float g_attn[NN*HH];
__device__ float g_hid [NN*128];
__device__ int   g_rowptr[NN+1];
__device__ int   g_cursor[NN];
__device__ int   g_esrc [EE];
__device__ float g_enorm[EE];
__device__ __nv_bfloat16 g_Qb[8*NN*32];   // [h][n][d], pre-scaled by 1/sqrt(32)*log2e
__device__ __nv_bfloat16 g_Kb[8*NN*32];   // [h][n][d]
__device__ __nv_bfloat16 g_Vb[8*32*NN];   // [h][d][n]  (transposed)

// ---------------- tf32 helpers ---------------------------------------------------
__device__ __forceinline__ uint32_t f2tf32(float f) {
    uint32_t u;
    asm("cvt.rna.tf32.f32 %0, %1;" : "=r"(u) : "f"(f));
    return u;
}
__device__ __forceinline__ uint4 f2tf32x4(float4 v) {
    return make_uint4(f2tf32(v.x), f2tf32(v.y), f2tf32(v.z), f2tf32(v.w));
}
__device__ __forceinline__ void mma_tf32(float* c, const uint32_t* a, uint32_t b0, uint32_t b1) {
    asm volatile(
        "mma.sync.aligned.m16n8k8.row.col.f32.tf32.tf32.f32 "
        "{%0,%1,%2,%3}, {%4,%5,%6,%7}, {%8,%9}, {%0,%1,%2,%3};\n"
        : "+f"(c[0]), "+f"(c[1]), "+f"(c[2]), "+f"(c[3])
        : "r"(a[0]), "r"(a[1]), "r"(a[2]), "r"(a[3]), "r"(b0), "r"(b1));
}

// ---------------- tf32 tensor-core GEMM ------------------------------------------
// C[M,N] = A[M,K] @ B (+bias)(+SRC)(relu).  TRANSB: B is [N,K] (torch weight).
// Block tile 128x64, BK=16, 8 warps (4x2), warp tile 32x32 via m16n8k8.
template<bool TRANSB, bool RELU, bool ADDSRC>
__global__ void __launch_bounds__(256) gemm_tf32(
    const float* __restrict__ A, const float* __restrict__ B,
    const float* __restrict__ bias, const float* __restrict__ SRC,
    float* __restrict__ C, int M, int N, int K)
{
    __shared__ uint32_t As[128*20];      // [m][k], stride 20 (conflict-free frags)
    __shared__ uint32_t Bs[1280];        // TRANSB: [n][k] stride 20; else [k][n] stride 72

    const int tid  = threadIdx.x;
    const int w    = tid >> 5, lane = tid & 31;
    const int g    = lane >> 2, t = lane & 3;
    const int wm   = w & 3, wn = w >> 2;
    const int m0   = blockIdx.y * 128, n0 = blockIdx.x * 64;

    float acc[2][4][4] = {};

    for (int k0 = 0; k0 < K; k0 += 16) {
        #pragma unroll
        for (int i = 0; i < 2; i++) {
            int idx = tid + i*256;              // 0..511
            int r = idx >> 2, c4 = (idx & 3) * 4;
            float4 v = *(const float4*)(A + (size_t)(m0 + r)*K + k0 + c4);
            *(uint4*)(&As[r*20 + c4]) = f2tf32x4(v);
        }
        if (TRANSB) {
            int n = tid >> 2, c4 = (tid & 3) * 4;
            float4 v = *(const float4*)(B + (size_t)(n0 + n)*K + k0 + c4);
            *(uint4*)(&Bs[n*20 + c4]) = f2tf32x4(v);
        } else {
            int r = tid >> 4, c4 = (tid & 15) * 4;
            float4 v = *(const float4*)(B + (size_t)(k0 + r)*N + n0 + c4);
            *(uint4*)(&Bs[r*72 + c4]) = f2tf32x4(v);
        }
        __syncthreads();

        #pragma unroll
        for (int ks = 0; ks < 2; ks++) {
            const int kb = ks * 8;
            uint32_t a[2][4];
            #pragma unroll
            for (int mt = 0; mt < 2; mt++) {
                int row = wm*32 + mt*16 + g;
                a[mt][0] = As[(row  )*20 + kb + t];
                a[mt][1] = As[(row+8)*20 + kb + t];
                a[mt][2] = As[(row  )*20 + kb + t + 4];
                a[mt][3] = As[(row+8)*20 + kb + t + 4];
            }
            #pragma unroll
            for (int nt = 0; nt < 4; nt++) {
                int n = wn*32 + nt*8 + g;
                uint32_t b0, b1;
                if (TRANSB) { b0 = Bs[n*20 + kb + t];     b1 = Bs[n*20 + kb + t + 4]; }
                else        { b0 = Bs[(kb+t)*72 + n];     b1 = Bs[(kb+t+4)*72 + n];   }
                mma_tf32(acc[0][nt], a[0], b0, b1);
                mma_tf32(acc[1][nt], a[1], b0, b1);
            }
        }
        __syncthreads();
    }

    #pragma unroll
    for (int mt = 0; mt < 2; mt++) {
        const int r0 = m0 + wm*32 + mt*16 + g;
        #pragma unroll
        for (int nt = 0; nt < 4; nt++) {
            const int n = n0 + wn*32 + nt*8 + 2*t;
            float bb0 = bias ? bias[n] : 0.f;
            float bb1 = bias ? bias[n+1] : 0.f;
            float v00 = acc[mt][nt][0] + bb0, v01 = acc[mt][nt][1] + bb1;
            float v10 = acc[mt][nt][2] + bb0, v11 = acc[mt][nt][3] + bb1;
            if (ADDSRC) {
                v00 += SRC[(size_t)r0*N + n];     v01 += SRC[(size_t)r0*N + n + 1];
                v10 += SRC[(size_t)(r0+8)*N + n]; v11 += SRC[(size_t)(r0+8)*N + n + 1];
            }
            if (RELU) {
                v00 = fmaxf(v00, 0.f); v01 = fmaxf(v01, 0.f);
                v10 = fmaxf(v10, 0.f); v11 = fmaxf(v11, 0.f);
            }
            *(float2*)(C + (size_t)r0*N + n)     = make_float2(v00, v01);
            *(float2*)(C + (size_t)(r0+8)*N + n) = make_float2(v10, v11);
        }
    }
}

// ---------------- graph preprocessing (CSR build) --------------------------------
__global__ void deg_count(const int* __restrict__ dst) {
    int e = blockIdx.x * 256 + threadIdx.x;
    if (e < EE) atomicAdd(&g_deg[dst[e]], 1.0f);
}

__global__ void compute_dinv() {
    int n = blockIdx.x * 256 + threadIdx.x;
    if (n < NN) g_dinv[n] = rsqrtf(g_deg[n] + 1.0f);
}

// one block, 1024 threads, 4 counts each -> exclusive prefix into rowptr + cursor
__global__ void __launch_bounds__(1024) scan_rowptr() {
    __shared__ int warpsum[32];
    const int tid = threadIdx.x;
    const int lane = tid & 31, wid = tid >> 5;
    const int base = tid * 4;
    int c[4], s = 0;
    #pragma unroll
    for (int j = 0; j < 4; j++) { c[j] = (int)g_deg[base + j]; s += c[j]; }
    int pre = s;
    #pragma unroll
    for (int off = 1; off < 32; off <<= 1) {
        int v = __shfl_up_sync(0xffffffffu, pre, off);
        if (lane >= off) pre += v;
    }
    if (lane == 31) warpsum[wid] = pre;
    __syncthreads();
    if (wid == 0) {
        int v = warpsum[lane];
        #pragma unroll
        for (int off = 1; off < 32; off <<= 1) {
            int u = __shfl_up_sync(0xffffffffu, v, off);
            if (lane >= off) v += u;
        }
        warpsum[lane] = v;
    }
    __syncthreads();
    int excl = pre - s + (wid > 0 ? warpsum[wid-1] : 0);
    int run = excl;
    #pragma unroll
    for (int j = 0; j < 4; j++) {
        g_rowptr[base + j] = run;
        g_cursor[base + j] = run;
        run += c[j];
    }
    if (tid == 1023) g_rowptr[NN] = run;
}

__global__ void csr_scatter(const int* __restrict__ src, const int* __restrict__ dst) {
    int e = blockIdx.x * 256 + threadIdx.x;
    if (e >= EE) return;
    int s = src[e], d = dst[e];
    int p = atomicAdd(&g_cursor[d], 1);
    g_esrc[p]  = s;
    g_enorm[p] = g_dinv[s] * g_dinv[d];
}

// ---------------- GCN gather (one warp per node, fused bias/self/relu) -----------
template<bool RELU>
__global__ void __launch_bounds__(256) gcn_gather(const float* __restrict__ bias,
                                                  float* __restrict__ out) {
    const int node = blockIdx.x * 8 + (threadIdx.x >> 5);
    const int lane = threadIdx.x & 31;
    const int beg = g_rowptr[node], end = g_rowptr[node+1];

    float a0=0.f,a1=0.f,a2=0.f,a3=0.f,a4=0.f,a5=0.f,a6=0.f,a7=0.f;
    for (int i = beg; i < end; i++) {
        int s = g_esrc[i];
        float wgt = g_enorm[i];
        const float4* p = (const float4*)(g_tmp + (size_t)s*HH + lane*8);
        float4 x0 = p[0], x1 = p[1];
        a0 = fmaf(wgt, x0.x, a0); a1 = fmaf(wgt, x0.y, a1);
        a2 = fmaf(wgt, x0.z, a2); a3 = fmaf(wgt, x0.w, a3);
        a4 = fmaf(wgt, x1.x, a4); a5 = fmaf(wgt, x1.y, a5);
        a6 = fmaf(wgt, x1.z, a6); a7 = fmaf(wgt, x1.w, a7);
    }
    float di = g_dinv[node];
    float sw = di * di;
    const float4* q = (const float4*)(g_tmp + (size_t)node*HH + lane*8);
    float4 s0 = q[0], s1 = q[1];
    const float4* bp = (const float4*)(bias + lane*8);
    float4 b0 = bp[0], b1 = bp[1];
    float o0 = fmaf(sw, s0.x, a0) + b0.x, o1 = fmaf(sw, s0.y, a1) + b0.y;
    float o2 = fmaf(sw, s0.z, a2) + b0.z, o3 = fmaf(sw, s0.w, a3) + b0.w;
    float o4 = fmaf(sw, s1.x, a4) + b1.x, o5 = fmaf(sw, s1.y, a5) + b1.y;
    float o6 = fmaf(sw, s1.z, a6) + b1.z, o7 = fmaf(sw, s1.w, a7) + b1.w;
    if (RELU) {
        o0 = fmaxf(o0,0.f); o1 = fmaxf(o1,0.f); o2 = fmaxf(o2,0.f); o3 = fmaxf(o3,0.f);
        o4 = fmaxf(o4,0.f); o5 = fmaxf(o5,0.f); o6 = fmaxf(o6,0.f); o7 = fmaxf(o7,0.f);
    }
    float4* op = (float4*)(out + (size_t)node*HH + lane*8);
    op[0] = make_float4(o0,o1,o2,o3);
    op[1] = make_float4(o4,o5,o6,o7);
}

// ---------------- bf16 conversion for attention ----------------------------------
__global__ void qkv_to_bf16() {
    int idx = blockIdx.x * 256 + threadIdx.x;      // NN*256
    int n = idx >> 8, c = idx & 255;
    int h = c >> 5, d = c & 31;
    const float QSCALE = 0.17677669529663687f * 1.4426950408889634f;
    float q = g_qkv[(size_t)n*768 + c] * QSCALE;
    float k = g_qkv[(size_t)n*768 + 256 + c];
    float v = g_qkv[(size_t)n*768 + 512 + c];
    g_Qb[((size_t)h*NN + n)*32 + d] = __float2bfloat16(q);
    g_Kb[((size_t)h*NN + n)*32 + d] = __float2bfloat16(k);
    g_Vb[((size_t)h*32 + d)*NN + n] = __float2bfloat16(v);
}

// ---------------- bf16 tensor-core flash attention --------------------------------
__device__ __forceinline__ void mma_bf16(float* c, const uint32_t* a, uint32_t b0, uint32_t b1) {
    asm volatile(
        "mma.sync.aligned.m16n8k16.row.col.f32.bf16.bf16.f32 "
        "{%0,%1,%2,%3}, {%4,%5,%6,%7}, {%8,%9}, {%0,%1,%2,%3};\n"
        : "+f"(c[0]), "+f"(c[1]), "+f"(c[2]), "+f"(c[3])
        : "r"(a[0]), "r"(a[1]), "r"(a[2]), "r"(a[3]), "r"(b0), "r"(b1));
}

__device__ __forceinline__ uint32_t pack_bf16(float lo, float hi) {
    __nv_bfloat162 v = __floats2bfloat162_rn(lo, hi);
    return *(uint32_t*)&v;
}

__global__ void __launch_bounds__(256) flash_attn_bf16() {
    __shared__ __align__(16) char Ks[64*72];    // [key][36 halves]
    __shared__ __align__(16) char Vs[32*144];   // [d][72 halves]

    const int head = blockIdx.y;
    const int q0   = blockIdx.x * 128;
    const int tid  = threadIdx.x;
    const int w    = tid >> 5, lane = tid & 31;
    const int g    = lane >> 2, t = lane & 3;

    uint32_t aq[2][4];
    {
        const __nv_bfloat16* qb = g_Qb + ((size_t)head*NN + q0 + w*16) * 32;
        #pragma unroll
        for (int ks = 0; ks < 2; ks++) {
            int c = ks*16 + 2*t;
            aq[ks][0] = *(const uint32_t*)(qb + (size_t)(g  )*32 + c);
            aq[ks][1] = *(const uint32_t*)(qb + (size_t)(g+8)*32 + c);
            aq[ks][2] = *(const uint32_t*)(qb + (size_t)(g  )*32 + c + 8);
            aq[ks][3] = *(const uint32_t*)(qb + (size_t)(g+8)*32 + c + 8);
        }
    }

    float m0 = -1e30f, m1 = -1e30f, l0 = 0.f, l1 = 0.f;
    float o[4][4] = {};

    const __nv_bfloat16* kg = g_Kb + (size_t)head*NN*32;
    const __nv_bfloat16* vg = g_Vb + (size_t)head*32*NN;

    for (int kt = 0; kt < NN/64; kt++) {
        __syncthreads();
        {
            int r = tid >> 2, dp = (tid & 3) * 8;
            uint4 kv = *(const uint4*)(kg + (size_t)(kt*64 + r)*32 + dp);
            char* p = Ks + r*72 + dp*2;
            *(uint2*)(p)     = make_uint2(kv.x, kv.y);
            *(uint2*)(p + 8) = make_uint2(kv.z, kv.w);
            int d = tid >> 3, kp = (tid & 7) * 8;
            uint4 vv = *(const uint4*)(vg + (size_t)d*NN + kt*64 + kp);
            *(uint4*)(Vs + d*144 + kp*2) = vv;
        }
        __syncthreads();

        float s[8][4];
        #pragma unroll
        for (int nb = 0; nb < 8; nb++) {
            s[nb][0] = s[nb][1] = s[nb][2] = s[nb][3] = 0.f;
            const char* kr = Ks + (nb*8 + g)*72;
            uint32_t b0 = *(const uint32_t*)(kr + (2*t)*2);
            uint32_t b1 = *(const uint32_t*)(kr + (2*t+8)*2);
            mma_bf16(s[nb], aq[0], b0, b1);
            b0 = *(const uint32_t*)(kr + (16 + 2*t)*2);
            b1 = *(const uint32_t*)(kr + (16 + 2*t+8)*2);
            mma_bf16(s[nb], aq[1], b0, b1);
        }

        float tm0 = -1e30f, tm1 = -1e30f;
        #pragma unroll
        for (int nb = 0; nb < 8; nb++) {
            tm0 = fmaxf(tm0, fmaxf(s[nb][0], s[nb][1]));
            tm1 = fmaxf(tm1, fmaxf(s[nb][2], s[nb][3]));
        }
        tm0 = fmaxf(tm0, __shfl_xor_sync(0xffffffffu, tm0, 1));
        tm0 = fmaxf(tm0, __shfl_xor_sync(0xffffffffu, tm0, 2));
        tm1 = fmaxf(tm1, __shfl_xor_sync(0xffffffffu, tm1, 1));
        tm1 = fmaxf(tm1, __shfl_xor_sync(0xffffffffu, tm1, 2));
        float nm0 = fmaxf(m0, tm0), nm1 = fmaxf(m1, tm1);
        float al0 = exp2f(m0 - nm0), al1 = exp2f(m1 - nm1);
        m0 = nm0; m1 = nm1;
        float ps0 = 0.f, ps1 = 0.f;
        #pragma unroll
        for (int nb = 0; nb < 8; nb++) {
            s[nb][0] = exp2f(s[nb][0] - nm0);
            s[nb][1] = exp2f(s[nb][1] - nm0);
            s[nb][2] = exp2f(s[nb][2] - nm1);
            s[nb][3] = exp2f(s[nb][3] - nm1);
            ps0 += s[nb][0] + s[nb][1];
            ps1 += s[nb][2] + s[nb][3];
        }
        ps0 += __shfl_xor_sync(0xffffffffu, ps0, 1);
        ps0 += __shfl_xor_sync(0xffffffffu, ps0, 2);
        ps1 += __shfl_xor_sync(0xffffffffu, ps1, 1);
        ps1 += __shfl_xor_sync(0xffffffffu, ps1, 2);
        l0 = l0 * al0 + ps0;
        l1 = l1 * al1 + ps1;

        #pragma unroll
        for (int nbv = 0; nbv < 4; nbv++) {
            o[nbv][0] *= al0; o[nbv][1] *= al0;
            o[nbv][2] *= al1; o[nbv][3] *= al1;
        }
        uint32_t ap[4][4];
        #pragma unroll
        for (int s4 = 0; s4 < 4; s4++) {
            ap[s4][0] = pack_bf16(s[2*s4  ][0], s[2*s4  ][1]);
            ap[s4][1] = pack_bf16(s[2*s4  ][2], s[2*s4  ][3]);
            ap[s4][2] = pack_bf16(s[2*s4+1][0], s[2*s4+1][1]);
            ap[s4][3] = pack_bf16(s[2*s4+1][2], s[2*s4+1][3]);
        }

        #pragma unroll
        for (int nbv = 0; nbv < 4; nbv++) {
            const char* vr = Vs + (nbv*8 + g)*144;
            #pragma unroll
            for (int s4 = 0; s4 < 4; s4++) {
                uint32_t b0 = *(const uint32_t*)(vr + (16*s4 + 2*t)*2);
                uint32_t b1 = *(const uint32_t*)(vr + (16*s4 + 2*t + 8)*2);
                mma_bf16(o[nbv], ap[s4], b0, b1);
            }
        }
    }

    float inv0 = 1.0f / l0, inv1 = 1.0f / l1;
    int row0 = q0 + w*16 + g;
    #pragma unroll
    for (int nbv = 0; nbv < 4; nbv++) {
        int col = head*32 + nbv*8 + 2*t;
        *(float2*)(g_attn + (size_t)row0*HH + col)       = make_float2(o[nbv][0]*inv0, o[nbv][1]*inv0);
        *(float2*)(g_attn + (size_t)(row0+8)*HH + col)   = make_float2(o[nbv][2]*inv1, o[nbv][3]*inv1);
    }
}

// ---------------- tiny output heads ---------------------------------------------
template<int C, bool SOFTMAX>
__global__ void head_kernel(const float* __restrict__ hid, const float* __restrict__ W,
                            const float* __restrict__ b, float* __restrict__ out) {
    __shared__ float sh[128];
    __shared__ float lg[16];
    const int n = blockIdx.x;
    const int t = threadIdx.x;
    sh[t] = hid[(size_t)n * 128 + t];
    __syncthreads();
    if (t < C) {
        float s = b[t];
        #pragma unroll 8
        for (int k = 0; k < 128; k++) s = fmaf(sh[k], W[t*128 + k], s);
        lg[t] = s;
    }
    __syncthreads();
    if (SOFTMAX) {
        if (t == 0) {
            float mx = lg[0];
            #pragma unroll
            for (int c = 1; c < C; c++) mx = fmaxf(mx, lg[c]);
            float e[C]; float sum = 0.f;
            #pragma unroll
            for (int c = 0; c < C; c++) { e[c] = __expf(lg[c] - mx); sum += e[c]; }
            float inv = 1.0f / sum;
            #pragma unroll
            for (int c = 0; c < C; c++) out[(size_t)n*C + c] = e[c] * inv;
        }
    } else {
        if (t < C) out[(size_t)n*C + t] = 1.0f / (1.0f + __expf(-lg[t]));
    }
}

// ---------------- launch ---------------------------------------------------------
extern "C" void kernel_launch(void* const* d_in, const int* in_sizes, int n_in,
                              void* d_out, int out_size)
{
    const float* x     = (const float*)d_in[0];
    const int*   ei    = (const int*)  d_in[1];
    const float* W1    = (const float*)d_in[2];
    const float* b1    = (const float*)d_in[3];
    const float* W2    = (const float*)d_in[4];
    const float* b2    = (const float*)d_in[5];
    const float* W3    = (const float*)d_in[6];
    const float* b3    = (const float*)d_in[7];
    const float* in_w  = (const float*)d_in[8];
    const float* in_b  = (const float*)d_in[9];
    const float* out_w = (const float*)d_in[10];
    const float* out_b = (const float*)d_in[11];
    const float* fp1w  = (const float*)d_in[12];
    const float* fp1b  = (const float*)d_in[13];
    const float* fp2w  = (const float*)d_in[14];
    const float* fp2b  = (const float*)d_in[15];
    const float* pd1w  = (const float*)d_in[16];
    const float* pd1b  = (const float*)d_in[17];
    const float* pd2w  = (const float*)d_in[18];
    const float* pd2b  = (const float*)d_in[19];
    const int* src = ei;
    const int* dst = ei + EE;
    float* outp = (float*)d_out;

    float *tmp, *h, *h3, *deg, *qkv, *attn, *hid;
    cudaGetSymbolAddress((void**)&tmp,  g_tmp);
    cudaGetSymbolAddress((void**)&h,    g_h);
    cudaGetSymbolAddress((void**)&h3,   g_h3);
    cudaGetSymbolAddress((void**)&deg,  g_deg);
    cudaGetSymbolAddress((void**)&qkv,  g_qkv);
    cudaGetSymbolAddress((void**)&attn, g_attn);
    cudaGetSymbolAddress((void**)&hid,  g_hid);

    // CSR build (once per launch)
    cudaMemsetAsync(deg, 0, NN * sizeof(float), 0);
    deg_count<<<EE/256, 256>>>(dst);
    compute_dinv<<<NN/256, 256>>>();
    scan_rowptr<<<1, 1024>>>();
    csr_scatter<<<EE/256, 256>>>(src, dst);

    const dim3 blk(256);

    // GCN layer 1: tmp = x @ W1 ; gather+bias+relu -> h
    gemm_tf32<false,false,false><<<dim3(4,32), blk>>>(x, W1, nullptr, nullptr, tmp, NN, HH, 128);
    gcn_gather<true><<<NN/8, blk>>>(b1, h);

    // GCN layer 2
    gemm_tf32<false,false,false><<<dim3(4,32), blk>>>(h, W2, nullptr, nullptr, tmp, NN, HH, HH);
    gcn_gather<true><<<NN/8, blk>>>(b2, h);

    // GCN layer 3 (no relu) -> h3
    gemm_tf32<false,false,false><<<dim3(4,32), blk>>>(h, W3, nullptr, nullptr, tmp, NN, HH, HH);
    gcn_gather<false><<<NN/8, blk>>>(b3, h3);

    // MHA
    gemm_tf32<true,false,false><<<dim3(12,32), blk>>>(h3, in_w, in_b, nullptr, qkv, NN, 3*HH, HH);
    qkv_to_bf16<<<NN, 256>>>();
    flash_attn_bf16<<<dim3(NN/128, 8), blk>>>();
    gemm_tf32<true,false,true><<<dim3(4,32), blk>>>(attn, out_w, out_b, h3, h, NN, HH, HH);

    // heads
    gemm_tf32<true,true,false><<<dim3(2,32), blk>>>(h, fp1w, fp1b, nullptr, hid, NN, 128, HH);
    head_kernel<3, true><<<NN, 128>>>(hid, fp2w, fp2b, outp);

    gemm_tf32<true,true,false><<<dim3(2,32), blk>>>(h, pd1w, pd1b, nullptr, hid, NN, 128, HH);
    head_kernel<10, false><<<NN, 128>>>(hid, pd2w, pd2b, outp + (size_t)NN*3);
}

// round 5
// speedup vs baseline: 4.0440x; 1.3732x over previous
#include <cuda_runtime.h>
#include <cuda_bf16.h>
#include <cstdint>
#include <math.h>

#define NN 4096
#define EE 131072
#define HH 256

// ---------------- scratch (static device globals; no allocation) ----------------
__device__ float g_tmp [NN*HH];
__device__ float g_h   [NN*HH];
__device__ float g_h3  [NN*HH];
__device__ float g_deg [NN];
__device__ float g_dinv[NN];
__device__ float g_qkv [NN*3*HH];
__device__ float g_attn[NN*HH];
__device__ float g_hid [NN*128];
__device__ int   g_rowptr[NN+1];
__device__ int   g_cursor[NN];
__device__ int   g_esrc [EE];
__device__ float g_enorm[EE];
__device__ __nv_bfloat16 g_Qb[8*NN*32];   // [h][n][d], pre-scaled by 1/sqrt(32)*log2e
__device__ __nv_bfloat16 g_Kb[8*NN*32];   // [h][n][d]
__device__ __nv_bfloat16 g_Vb[8*32*NN];   // [h][d][n]  (transposed)

// ---------------- async-copy helpers ---------------------------------------------
__device__ __forceinline__ void cp_async16(void* smem, const void* gmem) {
    uint32_t s = (uint32_t)__cvta_generic_to_shared(smem);
    asm volatile("cp.async.ca.shared.global [%0], [%1], 16;\n" :: "r"(s), "l"(gmem));
}
#define CP_COMMIT() asm volatile("cp.async.commit_group;\n" ::: "memory")
#define CP_WAIT(n)  asm volatile("cp.async.wait_group %0;\n" :: "n"(n) : "memory")

// ---------------- mma wrappers ----------------------------------------------------
__device__ __forceinline__ void mma_tf32(float* c, const uint32_t* a, uint32_t b0, uint32_t b1) {
    asm volatile(
        "mma.sync.aligned.m16n8k8.row.col.f32.tf32.tf32.f32 "
        "{%0,%1,%2,%3}, {%4,%5,%6,%7}, {%8,%9}, {%0,%1,%2,%3};\n"
        : "+f"(c[0]), "+f"(c[1]), "+f"(c[2]), "+f"(c[3])
        : "r"(a[0]), "r"(a[1]), "r"(a[2]), "r"(a[3]), "r"(b0), "r"(b1));
}
__device__ __forceinline__ void mma_bf16(float* c, const uint32_t* a, uint32_t b0, uint32_t b1) {
    asm volatile(
        "mma.sync.aligned.m16n8k16.row.col.f32.bf16.bf16.f32 "
        "{%0,%1,%2,%3}, {%4,%5,%6,%7}, {%8,%9}, {%0,%1,%2,%3};\n"
        : "+f"(c[0]), "+f"(c[1]), "+f"(c[2]), "+f"(c[3])
        : "r"(a[0]), "r"(a[1]), "r"(a[2]), "r"(a[3]), "r"(b0), "r"(b1));
}
__device__ __forceinline__ uint32_t pack_bf16(float lo, float hi) {
    __nv_bfloat162 v = __floats2bfloat162_rn(lo, hi);
    return *(uint32_t*)&v;
}

// ---------------- pipelined tf32 GEMM --------------------------------------------
// C[M,N] = A[M,K] @ B (+bias)(+SRC)(relu).  TRANSB: B is [N,K] (torch weight).
// Block tile 128x64, BK=16, 8 warps (4x2), warp tile 32x32 via m16n8k8.
// fp32 bits fed directly as tf32 operands (truncation) — no cvt pass.
template<bool TRANSB, bool RELU, bool ADDSRC>
__global__ void __launch_bounds__(256) gemm_tf32(
    const float* __restrict__ A, const float* __restrict__ B,
    const float* __restrict__ bias, const float* __restrict__ SRC,
    float* __restrict__ C, int M, int N, int K)
{
    __shared__ float As[2][128*20];     // [m][k] stride 20 floats (80B, 16B-aligned rows)
    __shared__ float Bs[2][1280];       // TRANSB: [n][k] s20; else [k][n] s72

    const int tid  = threadIdx.x;
    const int w    = tid >> 5, lane = tid & 31;
    const int g    = lane >> 2, t = lane & 3;
    const int wm   = w & 3, wn = w >> 2;
    const int m0   = blockIdx.y * 128, n0 = blockIdx.x * 64;
    const int KT   = K >> 4;

    const int ar  = tid >> 2, ac4 = (tid & 3) * 4;           // A chunk coords
    const int bnr = tid >> 2, bnc = (tid & 3) * 4;           // B TRANSB coords
    const int bkr = tid >> 4, bkc = (tid & 15) * 4;          // B non-TRANSB coords

    float acc[2][4][4] = {};

    // prologue: stage 0
    {
        cp_async16(&As[0][ar*20 + ac4],        A + (size_t)(m0 + ar)*K + ac4);
        cp_async16(&As[0][(ar+64)*20 + ac4],   A + (size_t)(m0 + ar + 64)*K + ac4);
        if (TRANSB) cp_async16(&Bs[0][bnr*20 + bnc], B + (size_t)(n0 + bnr)*K + bnc);
        else        cp_async16(&Bs[0][bkr*72 + bkc], B + (size_t)bkr*N + n0 + bkc);
        CP_COMMIT();
    }

    for (int kt = 0; kt < KT; kt++) {
        const int st = kt & 1;
        if (kt + 1 < KT) {
            const int k0 = (kt + 1) << 4;
            cp_async16(&As[st^1][ar*20 + ac4],      A + (size_t)(m0 + ar)*K + k0 + ac4);
            cp_async16(&As[st^1][(ar+64)*20 + ac4], A + (size_t)(m0 + ar + 64)*K + k0 + ac4);
            if (TRANSB) cp_async16(&Bs[st^1][bnr*20 + bnc], B + (size_t)(n0 + bnr)*K + k0 + bnc);
            else        cp_async16(&Bs[st^1][bkr*72 + bkc], B + (size_t)(k0 + bkr)*N + n0 + bkc);
            CP_COMMIT();
            CP_WAIT(1);
        } else {
            CP_WAIT(0);
        }
        __syncthreads();

        const uint32_t* as = (const uint32_t*)As[st];
        const uint32_t* bs = (const uint32_t*)Bs[st];
        #pragma unroll
        for (int ks = 0; ks < 2; ks++) {
            const int kb = ks * 8;
            uint32_t a[2][4];
            #pragma unroll
            for (int mt = 0; mt < 2; mt++) {
                int row = wm*32 + mt*16 + g;
                a[mt][0] = as[(row  )*20 + kb + t];
                a[mt][1] = as[(row+8)*20 + kb + t];
                a[mt][2] = as[(row  )*20 + kb + t + 4];
                a[mt][3] = as[(row+8)*20 + kb + t + 4];
            }
            #pragma unroll
            for (int nt = 0; nt < 4; nt++) {
                int n = wn*32 + nt*8 + g;
                uint32_t b0, b1;
                if (TRANSB) { b0 = bs[n*20 + kb + t];  b1 = bs[n*20 + kb + t + 4]; }
                else        { b0 = bs[(kb+t)*72 + n];  b1 = bs[(kb+t+4)*72 + n];   }
                mma_tf32(acc[0][nt], a[0], b0, b1);
                mma_tf32(acc[1][nt], a[1], b0, b1);
            }
        }
        __syncthreads();
    }

    #pragma unroll
    for (int mt = 0; mt < 2; mt++) {
        const int r0 = m0 + wm*32 + mt*16 + g;
        #pragma unroll
        for (int nt = 0; nt < 4; nt++) {
            const int n = n0 + wn*32 + nt*8 + 2*t;
            float bb0 = bias ? bias[n] : 0.f;
            float bb1 = bias ? bias[n+1] : 0.f;
            float v00 = acc[mt][nt][0] + bb0, v01 = acc[mt][nt][1] + bb1;
            float v10 = acc[mt][nt][2] + bb0, v11 = acc[mt][nt][3] + bb1;
            if (ADDSRC) {
                v00 += SRC[(size_t)r0*N + n];     v01 += SRC[(size_t)r0*N + n + 1];
                v10 += SRC[(size_t)(r0+8)*N + n]; v11 += SRC[(size_t)(r0+8)*N + n + 1];
            }
            if (RELU) {
                v00 = fmaxf(v00, 0.f); v01 = fmaxf(v01, 0.f);
                v10 = fmaxf(v10, 0.f); v11 = fmaxf(v11, 0.f);
            }
            *(float2*)(C + (size_t)r0*N + n)     = make_float2(v00, v01);
            *(float2*)(C + (size_t)(r0+8)*N + n) = make_float2(v10, v11);
        }
    }
}

// ---------------- graph preprocessing (CSR build) --------------------------------
__global__ void deg_count(const int* __restrict__ dst) {
    int e = blockIdx.x * 256 + threadIdx.x;
    if (e < EE) atomicAdd(&g_deg[dst[e]], 1.0f);
}

__global__ void compute_dinv() {
    int n = blockIdx.x * 256 + threadIdx.x;
    if (n < NN) g_dinv[n] = rsqrtf(g_deg[n] + 1.0f);
}

__global__ void __launch_bounds__(1024) scan_rowptr() {
    __shared__ int warpsum[32];
    const int tid = threadIdx.x;
    const int lane = tid & 31, wid = tid >> 5;
    const int base = tid * 4;
    int c[4], s = 0;
    #pragma unroll
    for (int j = 0; j < 4; j++) { c[j] = (int)g_deg[base + j]; s += c[j]; }
    int pre = s;
    #pragma unroll
    for (int off = 1; off < 32; off <<= 1) {
        int v = __shfl_up_sync(0xffffffffu, pre, off);
        if (lane >= off) pre += v;
    }
    if (lane == 31) warpsum[wid] = pre;
    __syncthreads();
    if (wid == 0) {
        int v = warpsum[lane];
        #pragma unroll
        for (int off = 1; off < 32; off <<= 1) {
            int u = __shfl_up_sync(0xffffffffu, v, off);
            if (lane >= off) v += u;
        }
        warpsum[lane] = v;
    }
    __syncthreads();
    int excl = pre - s + (wid > 0 ? warpsum[wid-1] : 0);
    int run = excl;
    #pragma unroll
    for (int j = 0; j < 4; j++) {
        g_rowptr[base + j] = run;
        g_cursor[base + j] = run;
        run += c[j];
    }
    if (tid == 1023) g_rowptr[NN] = run;
}

__global__ void csr_scatter(const int* __restrict__ src, const int* __restrict__ dst) {
    int e = blockIdx.x * 256 + threadIdx.x;
    if (e >= EE) return;
    int s = src[e], d = dst[e];
    int p = atomicAdd(&g_cursor[d], 1);
    g_esrc[p]  = s;
    g_enorm[p] = g_dinv[s] * g_dinv[d];
}

// ---------------- GCN gather (one warp per node, fused bias/self/relu) -----------
template<bool RELU>
__global__ void __launch_bounds__(256) gcn_gather(const float* __restrict__ bias,
                                                  float* __restrict__ out) {
    const int node = blockIdx.x * 8 + (threadIdx.x >> 5);
    const int lane = threadIdx.x & 31;
    const int beg = g_rowptr[node], end = g_rowptr[node+1];

    float a0=0.f,a1=0.f,a2=0.f,a3=0.f,a4=0.f,a5=0.f,a6=0.f,a7=0.f;
    for (int i = beg; i < end; i++) {
        int s = g_esrc[i];
        float wgt = g_enorm[i];
        const float4* p = (const float4*)(g_tmp + (size_t)s*HH + lane*8);
        float4 x0 = p[0], x1 = p[1];
        a0 = fmaf(wgt, x0.x, a0); a1 = fmaf(wgt, x0.y, a1);
        a2 = fmaf(wgt, x0.z, a2); a3 = fmaf(wgt, x0.w, a3);
        a4 = fmaf(wgt, x1.x, a4); a5 = fmaf(wgt, x1.y, a5);
        a6 = fmaf(wgt, x1.z, a6); a7 = fmaf(wgt, x1.w, a7);
    }
    float di = g_dinv[node];
    float sw = di * di;
    const float4* q = (const float4*)(g_tmp + (size_t)node*HH + lane*8);
    float4 s0 = q[0], s1 = q[1];
    const float4* bp = (const float4*)(bias + lane*8);
    float4 b0 = bp[0], b1 = bp[1];
    float o0 = fmaf(sw, s0.x, a0) + b0.x, o1 = fmaf(sw, s0.y, a1) + b0.y;
    float o2 = fmaf(sw, s0.z, a2) + b0.z, o3 = fmaf(sw, s0.w, a3) + b0.w;
    float o4 = fmaf(sw, s1.x, a4) + b1.x, o5 = fmaf(sw, s1.y, a5) + b1.y;
    float o6 = fmaf(sw, s1.z, a6) + b1.z, o7 = fmaf(sw, s1.w, a7) + b1.w;
    if (RELU) {
        o0 = fmaxf(o0,0.f); o1 = fmaxf(o1,0.f); o2 = fmaxf(o2,0.f); o3 = fmaxf(o3,0.f);
        o4 = fmaxf(o4,0.f); o5 = fmaxf(o5,0.f); o6 = fmaxf(o6,0.f); o7 = fmaxf(o7,0.f);
    }
    float4* op = (float4*)(out + (size_t)node*HH + lane*8);
    op[0] = make_float4(o0,o1,o2,o3);
    op[1] = make_float4(o4,o5,o6,o7);
}

// ---------------- bf16 conversion + V transpose (tiled, coalesced) ----------------
// grid (NN/64, 8 heads), block 256.
__global__ void __launch_bounds__(256) qkv_to_bf16() {
    __shared__ __nv_bfloat16 vt[32][72];   // [d][node] padded
    const int h  = blockIdx.y;
    const int n0 = blockIdx.x * 64;
    const int tid = threadIdx.x;
    const int n  = tid >> 2, c8 = (tid & 3) * 8;     // node-local, d-chunk
    const float QSCALE = 0.17677669529663687f * 1.4426950408889634f;

    const float* base = g_qkv + (size_t)(n0 + n)*768 + h*32 + c8;
    float4 q0 = *(const float4*)(base);
    float4 q1 = *(const float4*)(base + 4);
    float4 k0 = *(const float4*)(base + 256);
    float4 k1 = *(const float4*)(base + 260);
    float4 v0 = *(const float4*)(base + 512);
    float4 v1 = *(const float4*)(base + 516);

    uint4 qo = make_uint4(pack_bf16(q0.x*QSCALE, q0.y*QSCALE), pack_bf16(q0.z*QSCALE, q0.w*QSCALE),
                          pack_bf16(q1.x*QSCALE, q1.y*QSCALE), pack_bf16(q1.z*QSCALE, q1.w*QSCALE));
    uint4 ko = make_uint4(pack_bf16(k0.x, k0.y), pack_bf16(k0.z, k0.w),
                          pack_bf16(k1.x, k1.y), pack_bf16(k1.z, k1.w));
    *(uint4*)(g_Qb + ((size_t)h*NN + n0 + n)*32 + c8) = qo;
    *(uint4*)(g_Kb + ((size_t)h*NN + n0 + n)*32 + c8) = ko;

    vt[c8+0][n] = __float2bfloat16(v0.x); vt[c8+1][n] = __float2bfloat16(v0.y);
    vt[c8+2][n] = __float2bfloat16(v0.z); vt[c8+3][n] = __float2bfloat16(v0.w);
    vt[c8+4][n] = __float2bfloat16(v1.x); vt[c8+5][n] = __float2bfloat16(v1.y);
    vt[c8+6][n] = __float2bfloat16(v1.z); vt[c8+7][n] = __float2bfloat16(v1.w);
    __syncthreads();

    const int d = tid >> 3, k8 = (tid & 7) * 8;
    *(uint4*)(g_Vb + ((size_t)h*32 + d)*NN + n0 + k8) = *(uint4*)(&vt[d][k8]);
}

// ---------------- bf16 tensor-core flash attention (cp.async pipelined) -----------
// grid (NN/128, 8 heads), block 256 = 8 warps; warp owns 16 query rows.
__global__ void __launch_bounds__(256) flash_attn_bf16() {
    __shared__ __align__(16) char Ks[2][64*80];    // [key][40 halves], 16B-aligned rows
    __shared__ __align__(16) char Vs[2][32*144];   // [d][72 halves]

    const int head = blockIdx.y;
    const int q0   = blockIdx.x * 128;
    const int tid  = threadIdx.x;
    const int w    = tid >> 5, lane = tid & 31;
    const int g    = lane >> 2, t = lane & 3;

    const __nv_bfloat16* kg = g_Kb + (size_t)head*NN*32;
    const __nv_bfloat16* vg = g_Vb + (size_t)head*32*NN;

    const int kr8 = tid >> 2, kc8 = (tid & 3) * 8;   // K: row, 8-half chunk
    const int vd  = tid >> 3, vk8 = (tid & 7) * 8;   // V: d-row, 8-half chunk

    // prologue loads
    cp_async16(&Ks[0][kr8*80 + kc8*2], kg + (size_t)kr8*32 + kc8);
    cp_async16(&Vs[0][vd*144 + vk8*2], vg + (size_t)vd*NN + vk8);
    CP_COMMIT();

    // Q fragments
    uint32_t aq[2][4];
    {
        const __nv_bfloat16* qb = g_Qb + ((size_t)head*NN + q0 + w*16) * 32;
        #pragma unroll
        for (int ks = 0; ks < 2; ks++) {
            int c = ks*16 + 2*t;
            aq[ks][0] = *(const uint32_t*)(qb + (size_t)(g  )*32 + c);
            aq[ks][1] = *(const uint32_t*)(qb + (size_t)(g+8)*32 + c);
            aq[ks][2] = *(const uint32_t*)(qb + (size_t)(g  )*32 + c + 8);
            aq[ks][3] = *(const uint32_t*)(qb + (size_t)(g+8)*32 + c + 8);
        }
    }

    float m0 = -1e30f, m1 = -1e30f, l0 = 0.f, l1 = 0.f;
    float o[4][4] = {};

    for (int kt = 0; kt < NN/64; kt++) {
        const int st = kt & 1;
        if (kt + 1 < NN/64) {
            cp_async16(&Ks[st^1][kr8*80 + kc8*2], kg + (size_t)((kt+1)*64 + kr8)*32 + kc8);
            cp_async16(&Vs[st^1][vd*144 + vk8*2], vg + (size_t)vd*NN + (kt+1)*64 + vk8);
            CP_COMMIT();
            CP_WAIT(1);
        } else {
            CP_WAIT(0);
        }
        __syncthreads();

        // S = Q K^T : 8 n-blocks of 8 keys
        float s[8][4];
        #pragma unroll
        for (int nb = 0; nb < 8; nb++) {
            s[nb][0] = s[nb][1] = s[nb][2] = s[nb][3] = 0.f;
            const char* kr = Ks[st] + (nb*8 + g)*80;
            uint32_t b0 = *(const uint32_t*)(kr + (2*t)*2);
            uint32_t b1 = *(const uint32_t*)(kr + (2*t+8)*2);
            mma_bf16(s[nb], aq[0], b0, b1);
            b0 = *(const uint32_t*)(kr + (16 + 2*t)*2);
            b1 = *(const uint32_t*)(kr + (16 + 2*t+8)*2);
            mma_bf16(s[nb], aq[1], b0, b1);
        }

        // online softmax (log2 domain)
        float tm0 = -1e30f, tm1 = -1e30f;
        #pragma unroll
        for (int nb = 0; nb < 8; nb++) {
            tm0 = fmaxf(tm0, fmaxf(s[nb][0], s[nb][1]));
            tm1 = fmaxf(tm1, fmaxf(s[nb][2], s[nb][3]));
        }
        tm0 = fmaxf(tm0, __shfl_xor_sync(0xffffffffu, tm0, 1));
        tm0 = fmaxf(tm0, __shfl_xor_sync(0xffffffffu, tm0, 2));
        tm1 = fmaxf(tm1, __shfl_xor_sync(0xffffffffu, tm1, 1));
        tm1 = fmaxf(tm1, __shfl_xor_sync(0xffffffffu, tm1, 2));
        float nm0 = fmaxf(m0, tm0), nm1 = fmaxf(m1, tm1);
        float al0 = exp2f(m0 - nm0), al1 = exp2f(m1 - nm1);
        m0 = nm0; m1 = nm1;
        float ps0 = 0.f, ps1 = 0.f;
        #pragma unroll
        for (int nb = 0; nb < 8; nb++) {
            s[nb][0] = exp2f(s[nb][0] - nm0);
            s[nb][1] = exp2f(s[nb][1] - nm0);
            s[nb][2] = exp2f(s[nb][2] - nm1);
            s[nb][3] = exp2f(s[nb][3] - nm1);
            ps0 += s[nb][0] + s[nb][1];
            ps1 += s[nb][2] + s[nb][3];
        }
        ps0 += __shfl_xor_sync(0xffffffffu, ps0, 1);
        ps0 += __shfl_xor_sync(0xffffffffu, ps0, 2);
        ps1 += __shfl_xor_sync(0xffffffffu, ps1, 1);
        ps1 += __shfl_xor_sync(0xffffffffu, ps1, 2);
        l0 = l0 * al0 + ps0;
        l1 = l1 * al1 + ps1;

        #pragma unroll
        for (int nbv = 0; nbv < 4; nbv++) {
            o[nbv][0] *= al0; o[nbv][1] *= al0;
            o[nbv][2] *= al1; o[nbv][3] *= al1;
        }
        uint32_t ap[4][4];
        #pragma unroll
        for (int s4 = 0; s4 < 4; s4++) {
            ap[s4][0] = pack_bf16(s[2*s4  ][0], s[2*s4  ][1]);
            ap[s4][1] = pack_bf16(s[2*s4  ][2], s[2*s4  ][3]);
            ap[s4][2] = pack_bf16(s[2*s4+1][0], s[2*s4+1][1]);
            ap[s4][3] = pack_bf16(s[2*s4+1][2], s[2*s4+1][3]);
        }

        #pragma unroll
        for (int nbv = 0; nbv < 4; nbv++) {
            const char* vr = Vs[st] + (nbv*8 + g)*144;
            #pragma unroll
            for (int s4 = 0; s4 < 4; s4++) {
                uint32_t b0 = *(const uint32_t*)(vr + (16*s4 + 2*t)*2);
                uint32_t b1 = *(const uint32_t*)(vr + (16*s4 + 2*t + 8)*2);
                mma_bf16(o[nbv], ap[s4], b0, b1);
            }
        }
        __syncthreads();
    }

    float inv0 = 1.0f / l0, inv1 = 1.0f / l1;
    int row0 = q0 + w*16 + g;
    #pragma unroll
    for (int nbv = 0; nbv < 4; nbv++) {
        int col = head*32 + nbv*8 + 2*t;
        *(float2*)(g_attn + (size_t)row0*HH + col)       = make_float2(o[nbv][0]*inv0, o[nbv][1]*inv0);
        *(float2*)(g_attn + (size_t)(row0+8)*HH + col)   = make_float2(o[nbv][2]*inv1, o[nbv][3]*inv1);
    }
}

// ---------------- output heads (warp per node) ------------------------------------
template<int C, bool SOFTMAX>
__global__ void __launch_bounds__(256) head_warp(const float* __restrict__ hid,
                                                 const float* __restrict__ W,
                                                 const float* __restrict__ b,
                                                 float* __restrict__ out) {
    const int node = blockIdx.x * 8 + (threadIdx.x >> 5);
    const int lane = threadIdx.x & 31;
    float4 hv = *(const float4*)(hid + (size_t)node*128 + lane*4);
    float lg[C];
    #pragma unroll
    for (int c = 0; c < C; c++) {
        float4 wv = *(const float4*)(W + c*128 + lane*4);
        float d = hv.x*wv.x + hv.y*wv.y + hv.z*wv.z + hv.w*wv.w;
        #pragma unroll
        for (int m = 16; m >= 1; m >>= 1) d += __shfl_xor_sync(0xffffffffu, d, m);
        lg[c] = d + b[c];
    }
    if (lane == 0) {
        if (SOFTMAX) {
            float mx = lg[0];
            #pragma unroll
            for (int c = 1; c < C; c++) mx = fmaxf(mx, lg[c]);
            float e[C]; float sum = 0.f;
            #pragma unroll
            for (int c = 0; c < C; c++) { e[c] = __expf(lg[c] - mx); sum += e[c]; }
            float inv = 1.0f / sum;
            #pragma unroll
            for (int c = 0; c < C; c++) out[(size_t)node*C + c] = e[c] * inv;
        } else {
            #pragma unroll
            for (int c = 0; c < C; c++)
                out[(size_t)node*C + c] = 1.0f / (1.0f + __expf(-lg[c]));
        }
    }
}

// ---------------- launch ---------------------------------------------------------
extern "C" void kernel_launch(void* const* d_in, const int* in_sizes, int n_in,
                              void* d_out, int out_size)
{
    const float* x     = (const float*)d_in[0];
    const int*   ei    = (const int*)  d_in[1];
    const float* W1    = (const float*)d_in[2];
    const float* b1    = (const float*)d_in[3];
    const float* W2    = (const float*)d_in[4];
    const float* b2    = (const float*)d_in[5];
    const float* W3    = (const float*)d_in[6];
    const float* b3    = (const float*)d_in[7];
    const float* in_w  = (const float*)d_in[8];
    const float* in_b  = (const float*)d_in[9];
    const float* out_w = (const float*)d_in[10];
    const float* out_b = (const float*)d_in[11];
    const float* fp1w  = (const float*)d_in[12];
    const float* fp1b  = (const float*)d_in[13];
    const float* fp2w  = (const float*)d_in[14];
    const float* fp2b  = (const float*)d_in[15];
    const float* pd1w  = (const float*)d_in[16];
    const float* pd1b  = (const float*)d_in[17];
    const float* pd2w  = (const float*)d_in[18];
    const float* pd2b  = (const float*)d_in[19];
    const int* src = ei;
    const int* dst = ei + EE;
    float* outp = (float*)d_out;

    float *tmp, *h, *h3, *deg, *qkv, *attn, *hid;
    cudaGetSymbolAddress((void**)&tmp,  g_tmp);
    cudaGetSymbolAddress((void**)&h,    g_h);
    cudaGetSymbolAddress((void**)&h3,   g_h3);
    cudaGetSymbolAddress((void**)&deg,  g_deg);
    cudaGetSymbolAddress((void**)&qkv,  g_qkv);
    cudaGetSymbolAddress((void**)&attn, g_attn);
    cudaGetSymbolAddress((void**)&hid,  g_hid);

    // CSR build
    cudaMemsetAsync(deg, 0, NN * sizeof(float), 0);
    deg_count<<<EE/256, 256>>>(dst);
    compute_dinv<<<NN/256, 256>>>();
    scan_rowptr<<<1, 1024>>>();
    csr_scatter<<<EE/256, 256>>>(src, dst);

    const dim3 blk(256);

    // GCN layers
    gemm_tf32<false,false,false><<<dim3(4,32), blk>>>(x, W1, nullptr, nullptr, tmp, NN, HH, 128);
    gcn_gather<true><<<NN/8, blk>>>(b1, h);
    gemm_tf32<false,false,false><<<dim3(4,32), blk>>>(h, W2, nullptr, nullptr, tmp, NN, HH, HH);
    gcn_gather<true><<<NN/8, blk>>>(b2, h);
    gemm_tf32<false,false,false><<<dim3(4,32), blk>>>(h, W3, nullptr, nullptr, tmp, NN, HH, HH);
    gcn_gather<false><<<NN/8, blk>>>(b3, h3);

    // MHA
    gemm_tf32<true,false,false><<<dim3(12,32), blk>>>(h3, in_w, in_b, nullptr, qkv, NN, 3*HH, HH);
    qkv_to_bf16<<<dim3(NN/64, 8), blk>>>();
    flash_attn_bf16<<<dim3(NN/128, 8), blk>>>();
    gemm_tf32<true,false,true><<<dim3(4,32), blk>>>(attn, out_w, out_b, h3, h, NN, HH, HH);

    // heads
    gemm_tf32<true,true,false><<<dim3(2,32), blk>>>(h, fp1w, fp1b, nullptr, hid, NN, 128, HH);
    head_warp<3, true><<<NN/8, blk>>>(hid, fp2w, fp2b, outp);
    gemm_tf32<true,true,false><<<dim3(2,32), blk>>>(h, pd1w, pd1b, nullptr, hid, NN, 128, HH);
    head_warp<10, false><<<NN/8, blk>>>(hid, pd2w, pd2b, outp + (size_t)NN*3);
}

// round 6
// speedup vs baseline: 4.2998x; 1.0632x over previous
#include <cuda_runtime.h>
#include <cuda_bf16.h>
#include <cstdint>
#include <math.h>

#define NN 4096
#define EE 131072
#define HH 256

#define QSCALE_F (0.17677669529663687f * 1.4426950408889634f)

// ---------------- scratch (static device globals; no allocation) ----------------
__device__ float g_tmp [NN*HH];
__device__ float g_h   [NN*HH];
__device__ float g_h3  [NN*HH];
__device__ float g_deg [NN];
__device__ float g_dinv[NN];
__device__ float g_vtmp[NN*HH];      // V columns of qkv (fp32 staging)
__device__ float g_attn[NN*HH];
__device__ float g_hid [NN*128];
__device__ float g_hid2[NN*128];
__device__ int   g_rowptr[NN+1];
__device__ int   g_cursor[NN];
__device__ int   g_esrc [EE];
__device__ float g_enorm[EE];
__device__ __nv_bfloat16 g_Qb[8*NN*32];   // [h][n][d], pre-scaled by 1/sqrt(32)*log2e
__device__ __nv_bfloat16 g_Kb[8*NN*32];   // [h][n][d]
__device__ __nv_bfloat16 g_Vb[8*32*NN];   // [h][d][n]  (transposed)

// ---------------- async-copy helpers ---------------------------------------------
__device__ __forceinline__ void cp_async16(void* smem, const void* gmem) {
    uint32_t s = (uint32_t)__cvta_generic_to_shared(smem);
    asm volatile("cp.async.ca.shared.global [%0], [%1], 16;\n" :: "r"(s), "l"(gmem));
}
#define CP_COMMIT() asm volatile("cp.async.commit_group;\n" ::: "memory")
#define CP_WAIT(n)  asm volatile("cp.async.wait_group %0;\n" :: "n"(n) : "memory")

// ---------------- mma wrappers ----------------------------------------------------
__device__ __forceinline__ void mma_tf32(float* c, const uint32_t* a, uint32_t b0, uint32_t b1) {
    asm volatile(
        "mma.sync.aligned.m16n8k8.row.col.f32.tf32.tf32.f32 "
        "{%0,%1,%2,%3}, {%4,%5,%6,%7}, {%8,%9}, {%0,%1,%2,%3};\n"
        : "+f"(c[0]), "+f"(c[1]), "+f"(c[2]), "+f"(c[3])
        : "r"(a[0]), "r"(a[1]), "r"(a[2]), "r"(a[3]), "r"(b0), "r"(b1));
}
__device__ __forceinline__ void mma_bf16(float* c, const uint32_t* a, uint32_t b0, uint32_t b1) {
    asm volatile(
        "mma.sync.aligned.m16n8k16.row.col.f32.bf16.bf16.f32 "
        "{%0,%1,%2,%3}, {%4,%5,%6,%7}, {%8,%9}, {%0,%1,%2,%3};\n"
        : "+f"(c[0]), "+f"(c[1]), "+f"(c[2]), "+f"(c[3])
        : "r"(a[0]), "r"(a[1]), "r"(a[2]), "r"(a[3]), "r"(b0), "r"(b1));
}
__device__ __forceinline__ uint32_t pack_bf16(float lo, float hi) {
    __nv_bfloat162 v = __floats2bfloat162_rn(lo, hi);
    return *(uint32_t*)&v;
}

// QKV epilogue store: n in [0,768). Block-uniform type (64-col tiles).
__device__ __forceinline__ void store_qkv(int row, int n, float a, float b) {
    int d = n & 31;
    int hh = (n >> 5) & 7;
    if (n < 256) {
        *(uint32_t*)(g_Qb + ((size_t)hh*NN + row)*32 + d) = pack_bf16(a*QSCALE_F, b*QSCALE_F);
    } else if (n < 512) {
        *(uint32_t*)(g_Kb + ((size_t)hh*NN + row)*32 + d) = pack_bf16(a, b);
    } else {
        *(float2*)(g_vtmp + (size_t)row*256 + (n - 512)) = make_float2(a, b);
    }
}

// ---------------- pipelined tf32 GEMM --------------------------------------------
// C[M,N] = A[M,K] @ B (+bias)(+SRC)(relu).  TRANSB: B is [N,K] (torch weight).
// QKV: epilogue routes to g_Qb/g_Kb (bf16) and g_vtmp instead of C.
template<bool TRANSB, bool RELU, bool ADDSRC, bool QKV>
__global__ void __launch_bounds__(256) gemm_tf32(
    const float* __restrict__ A, const float* __restrict__ B,
    const float* __restrict__ bias, const float* __restrict__ SRC,
    float* __restrict__ C, int M, int N, int K)
{
    __shared__ float As[2][128*20];
    __shared__ float Bs[2][1280];

    const int tid  = threadIdx.x;
    const int w    = tid >> 5, lane = tid & 31;
    const int g    = lane >> 2, t = lane & 3;
    const int wm   = w & 3, wn = w >> 2;
    const int m0   = blockIdx.y * 128, n0 = blockIdx.x * 64;
    const int KT   = K >> 4;

    const int ar  = tid >> 2, ac4 = (tid & 3) * 4;
    const int bnr = tid >> 2, bnc = (tid & 3) * 4;
    const int bkr = tid >> 4, bkc = (tid & 15) * 4;

    float acc[2][4][4] = {};

    {
        cp_async16(&As[0][ar*20 + ac4],        A + (size_t)(m0 + ar)*K + ac4);
        cp_async16(&As[0][(ar+64)*20 + ac4],   A + (size_t)(m0 + ar + 64)*K + ac4);
        if (TRANSB) cp_async16(&Bs[0][bnr*20 + bnc], B + (size_t)(n0 + bnr)*K + bnc);
        else        cp_async16(&Bs[0][bkr*72 + bkc], B + (size_t)bkr*N + n0 + bkc);
        CP_COMMIT();
    }

    for (int kt = 0; kt < KT; kt++) {
        const int st = kt & 1;
        if (kt + 1 < KT) {
            const int k0 = (kt + 1) << 4;
            cp_async16(&As[st^1][ar*20 + ac4],      A + (size_t)(m0 + ar)*K + k0 + ac4);
            cp_async16(&As[st^1][(ar+64)*20 + ac4], A + (size_t)(m0 + ar + 64)*K + k0 + ac4);
            if (TRANSB) cp_async16(&Bs[st^1][bnr*20 + bnc], B + (size_t)(n0 + bnr)*K + k0 + bnc);
            else        cp_async16(&Bs[st^1][bkr*72 + bkc], B + (size_t)(k0 + bkr)*N + n0 + bkc);
            CP_COMMIT();
            CP_WAIT(1);
        } else {
            CP_WAIT(0);
        }
        __syncthreads();

        const uint32_t* as = (const uint32_t*)As[st];
        const uint32_t* bs = (const uint32_t*)Bs[st];
        #pragma unroll
        for (int ks = 0; ks < 2; ks++) {
            const int kb = ks * 8;
            uint32_t a[2][4];
            #pragma unroll
            for (int mt = 0; mt < 2; mt++) {
                int row = wm*32 + mt*16 + g;
                a[mt][0] = as[(row  )*20 + kb + t];
                a[mt][1] = as[(row+8)*20 + kb + t];
                a[mt][2] = as[(row  )*20 + kb + t + 4];
                a[mt][3] = as[(row+8)*20 + kb + t + 4];
            }
            #pragma unroll
            for (int nt = 0; nt < 4; nt++) {
                int n = wn*32 + nt*8 + g;
                uint32_t b0, b1;
                if (TRANSB) { b0 = bs[n*20 + kb + t];  b1 = bs[n*20 + kb + t + 4]; }
                else        { b0 = bs[(kb+t)*72 + n];  b1 = bs[(kb+t+4)*72 + n];   }
                mma_tf32(acc[0][nt], a[0], b0, b1);
                mma_tf32(acc[1][nt], a[1], b0, b1);
            }
        }
        __syncthreads();
    }

    #pragma unroll
    for (int mt = 0; mt < 2; mt++) {
        const int r0 = m0 + wm*32 + mt*16 + g;
        #pragma unroll
        for (int nt = 0; nt < 4; nt++) {
            const int n = n0 + wn*32 + nt*8 + 2*t;
            float bb0 = bias ? bias[n] : 0.f;
            float bb1 = bias ? bias[n+1] : 0.f;
            float v00 = acc[mt][nt][0] + bb0, v01 = acc[mt][nt][1] + bb1;
            float v10 = acc[mt][nt][2] + bb0, v11 = acc[mt][nt][3] + bb1;
            if (ADDSRC) {
                v00 += SRC[(size_t)r0*N + n];     v01 += SRC[(size_t)r0*N + n + 1];
                v10 += SRC[(size_t)(r0+8)*N + n]; v11 += SRC[(size_t)(r0+8)*N + n + 1];
            }
            if (RELU) {
                v00 = fmaxf(v00, 0.f); v01 = fmaxf(v01, 0.f);
                v10 = fmaxf(v10, 0.f); v11 = fmaxf(v11, 0.f);
            }
            if (QKV) {
                store_qkv(r0,     n, v00, v01);
                store_qkv(r0 + 8, n, v10, v11);
            } else {
                *(float2*)(C + (size_t)r0*N + n)     = make_float2(v00, v01);
                *(float2*)(C + (size_t)(r0+8)*N + n) = make_float2(v10, v11);
            }
        }
    }
}

// ---------------- graph preprocessing (CSR build) --------------------------------
__global__ void deg_count(const int* __restrict__ dst) {
    int e = blockIdx.x * 256 + threadIdx.x;
    if (e < EE) atomicAdd(&g_deg[dst[e]], 1.0f);
}

// one block, 1024 threads: rowptr scan + cursor + dinv
__global__ void __launch_bounds__(1024) scan_rowptr() {
    __shared__ int warpsum[32];
    const int tid = threadIdx.x;
    const int lane = tid & 31, wid = tid >> 5;
    const int base = tid * 4;
    int c[4], s = 0;
    #pragma unroll
    for (int j = 0; j < 4; j++) {
        c[j] = (int)g_deg[base + j];
        g_dinv[base + j] = rsqrtf((float)c[j] + 1.0f);
        s += c[j];
    }
    int pre = s;
    #pragma unroll
    for (int off = 1; off < 32; off <<= 1) {
        int v = __shfl_up_sync(0xffffffffu, pre, off);
        if (lane >= off) pre += v;
    }
    if (lane == 31) warpsum[wid] = pre;
    __syncthreads();
    if (wid == 0) {
        int v = warpsum[lane];
        #pragma unroll
        for (int off = 1; off < 32; off <<= 1) {
            int u = __shfl_up_sync(0xffffffffu, v, off);
            if (lane >= off) v += u;
        }
        warpsum[lane] = v;
    }
    __syncthreads();
    int excl = pre - s + (wid > 0 ? warpsum[wid-1] : 0);
    int run = excl;
    #pragma unroll
    for (int j = 0; j < 4; j++) {
        g_rowptr[base + j] = run;
        g_cursor[base + j] = run;
        run += c[j];
    }
    if (tid == 1023) g_rowptr[NN] = run;
}

__global__ void csr_scatter(const int* __restrict__ src, const int* __restrict__ dst) {
    int e = blockIdx.x * 256 + threadIdx.x;
    if (e >= EE) return;
    int s = src[e], d = dst[e];
    int p = atomicAdd(&g_cursor[d], 1);
    g_esrc[p]  = s;
    g_enorm[p] = g_dinv[s] * g_dinv[d];
}

// ---------------- GCN gather (one warp per node, unroll x2) ----------------------
template<bool RELU>
__global__ void __launch_bounds__(256) gcn_gather(const float* __restrict__ bias,
                                                  float* __restrict__ out) {
    const int node = blockIdx.x * 8 + (threadIdx.x >> 5);
    const int lane = threadIdx.x & 31;
    const int beg = g_rowptr[node], end = g_rowptr[node+1];

    float a0=0.f,a1=0.f,a2=0.f,a3=0.f,a4=0.f,a5=0.f,a6=0.f,a7=0.f;
    int i = beg;
    for (; i + 2 <= end; i += 2) {
        int s0i = g_esrc[i],   s1i = g_esrc[i+1];
        float w0 = g_enorm[i], w1 = g_enorm[i+1];
        const float4* p0 = (const float4*)(g_tmp + (size_t)s0i*HH + lane*8);
        const float4* p1 = (const float4*)(g_tmp + (size_t)s1i*HH + lane*8);
        float4 x0 = p0[0], x1 = p0[1], y0 = p1[0], y1 = p1[1];
        a0 = fmaf(w0, x0.x, a0); a1 = fmaf(w0, x0.y, a1);
        a2 = fmaf(w0, x0.z, a2); a3 = fmaf(w0, x0.w, a3);
        a4 = fmaf(w0, x1.x, a4); a5 = fmaf(w0, x1.y, a5);
        a6 = fmaf(w0, x1.z, a6); a7 = fmaf(w0, x1.w, a7);
        a0 = fmaf(w1, y0.x, a0); a1 = fmaf(w1, y0.y, a1);
        a2 = fmaf(w1, y0.z, a2); a3 = fmaf(w1, y0.w, a3);
        a4 = fmaf(w1, y1.x, a4); a5 = fmaf(w1, y1.y, a5);
        a6 = fmaf(w1, y1.z, a6); a7 = fmaf(w1, y1.w, a7);
    }
    if (i < end) {
        int s0i = g_esrc[i];
        float w0 = g_enorm[i];
        const float4* p0 = (const float4*)(g_tmp + (size_t)s0i*HH + lane*8);
        float4 x0 = p0[0], x1 = p0[1];
        a0 = fmaf(w0, x0.x, a0); a1 = fmaf(w0, x0.y, a1);
        a2 = fmaf(w0, x0.z, a2); a3 = fmaf(w0, x0.w, a3);
        a4 = fmaf(w0, x1.x, a4); a5 = fmaf(w0, x1.y, a5);
        a6 = fmaf(w0, x1.z, a6); a7 = fmaf(w0, x1.w, a7);
    }
    float di = g_dinv[node];
    float sw = di * di;
    const float4* q = (const float4*)(g_tmp + (size_t)node*HH + lane*8);
    float4 s0 = q[0], s1 = q[1];
    const float4* bp = (const float4*)(bias + lane*8);
    float4 b0 = bp[0], b1 = bp[1];
    float o0 = fmaf(sw, s0.x, a0) + b0.x, o1 = fmaf(sw, s0.y, a1) + b0.y;
    float o2 = fmaf(sw, s0.z, a2) + b0.z, o3 = fmaf(sw, s0.w, a3) + b0.w;
    float o4 = fmaf(sw, s1.x, a4) + b1.x, o5 = fmaf(sw, s1.y, a5) + b1.y;
    float o6 = fmaf(sw, s1.z, a6) + b1.z, o7 = fmaf(sw, s1.w, a7) + b1.w;
    if (RELU) {
        o0 = fmaxf(o0,0.f); o1 = fmaxf(o1,0.f); o2 = fmaxf(o2,0.f); o3 = fmaxf(o3,0.f);
        o4 = fmaxf(o4,0.f); o5 = fmaxf(o5,0.f); o6 = fmaxf(o6,0.f); o7 = fmaxf(o7,0.f);
    }
    float4* op = (float4*)(out + (size_t)node*HH + lane*8);
    op[0] = make_float4(o0,o1,o2,o3);
    op[1] = make_float4(o4,o5,o6,o7);
}

// ---------------- V transpose to bf16 [h][d][n] ----------------------------------
__global__ void __launch_bounds__(256) v_to_bf16() {
    __shared__ __nv_bfloat16 vt[32][72];
    const int h  = blockIdx.y;
    const int n0 = blockIdx.x * 64;
    const int tid = threadIdx.x;
    const int n  = tid >> 2, c8 = (tid & 3) * 8;

    const float* base = g_vtmp + (size_t)(n0 + n)*256 + h*32 + c8;
    float4 v0 = *(const float4*)(base);
    float4 v1 = *(const float4*)(base + 4);
    vt[c8+0][n] = __float2bfloat16(v0.x); vt[c8+1][n] = __float2bfloat16(v0.y);
    vt[c8+2][n] = __float2bfloat16(v0.z); vt[c8+3][n] = __float2bfloat16(v0.w);
    vt[c8+4][n] = __float2bfloat16(v1.x); vt[c8+5][n] = __float2bfloat16(v1.y);
    vt[c8+6][n] = __float2bfloat16(v1.z); vt[c8+7][n] = __float2bfloat16(v1.w);
    __syncthreads();

    const int d = tid >> 3, k8 = (tid & 7) * 8;
    *(uint4*)(g_Vb + ((size_t)h*32 + d)*NN + n0 + k8) = *(uint4*)(&vt[d][k8]);
}

// ---------------- bf16 flash attention (3-stage cp.async, 1 barrier/iter) ---------
__global__ void __launch_bounds__(256) flash_attn_bf16() {
    __shared__ __align__(16) char Ks[3][64*80];
    __shared__ __align__(16) char Vs[3][32*144];

    const int head = blockIdx.y;
    const int q0   = blockIdx.x * 128;
    const int tid  = threadIdx.x;
    const int w    = tid >> 5, lane = tid & 31;
    const int g    = lane >> 2, t = lane & 3;
    const int KT   = NN / 64;

    const __nv_bfloat16* kg = g_Kb + (size_t)head*NN*32;
    const __nv_bfloat16* vg = g_Vb + (size_t)head*32*NN;

    const int kr8 = tid >> 2, kc8 = (tid & 3) * 8;
    const int vd  = tid >> 3, vk8 = (tid & 7) * 8;

    // prologue: stages 0,1
    cp_async16(&Ks[0][kr8*80 + kc8*2], kg + (size_t)kr8*32 + kc8);
    cp_async16(&Vs[0][vd*144 + vk8*2], vg + (size_t)vd*NN + vk8);
    CP_COMMIT();
    cp_async16(&Ks[1][kr8*80 + kc8*2], kg + (size_t)(64 + kr8)*32 + kc8);
    cp_async16(&Vs[1][vd*144 + vk8*2], vg + (size_t)vd*NN + 64 + vk8);
    CP_COMMIT();

    uint32_t aq[2][4];
    {
        const __nv_bfloat16* qb = g_Qb + ((size_t)head*NN + q0 + w*16) * 32;
        #pragma unroll
        for (int ks = 0; ks < 2; ks++) {
            int c = ks*16 + 2*t;
            aq[ks][0] = *(const uint32_t*)(qb + (size_t)(g  )*32 + c);
            aq[ks][1] = *(const uint32_t*)(qb + (size_t)(g+8)*32 + c);
            aq[ks][2] = *(const uint32_t*)(qb + (size_t)(g  )*32 + c + 8);
            aq[ks][3] = *(const uint32_t*)(qb + (size_t)(g+8)*32 + c + 8);
        }
    }

    float m0 = -1e30f, m1 = -1e30f, l0 = 0.f, l1 = 0.f;
    float o[4][4] = {};

    for (int kt = 0; kt < KT; kt++) {
        const int st = kt % 3;
        if (kt + 1 < KT) { CP_WAIT(1); } else { CP_WAIT(0); }
        __syncthreads();      // kt's tile visible; stage (kt+2)%3 free for reuse
        if (kt + 2 < KT) {
            const int sp = (kt + 2) % 3;
            cp_async16(&Ks[sp][kr8*80 + kc8*2], kg + (size_t)((kt+2)*64 + kr8)*32 + kc8);
            cp_async16(&Vs[sp][vd*144 + vk8*2], vg + (size_t)vd*NN + (kt+2)*64 + vk8);
            CP_COMMIT();
        }

        float s[8][4];
        #pragma unroll
        for (int nb = 0; nb < 8; nb++) {
            s[nb][0] = s[nb][1] = s[nb][2] = s[nb][3] = 0.f;
            const char* kr = Ks[st] + (nb*8 + g)*80;
            uint32_t b0 = *(const uint32_t*)(kr + (2*t)*2);
            uint32_t b1 = *(const uint32_t*)(kr + (2*t+8)*2);
            mma_bf16(s[nb], aq[0], b0, b1);
            b0 = *(const uint32_t*)(kr + (16 + 2*t)*2);
            b1 = *(const uint32_t*)(kr + (16 + 2*t+8)*2);
            mma_bf16(s[nb], aq[1], b0, b1);
        }

        float tm0 = -1e30f, tm1 = -1e30f;
        #pragma unroll
        for (int nb = 0; nb < 8; nb++) {
            tm0 = fmaxf(tm0, fmaxf(s[nb][0], s[nb][1]));
            tm1 = fmaxf(tm1, fmaxf(s[nb][2], s[nb][3]));
        }
        tm0 = fmaxf(tm0, __shfl_xor_sync(0xffffffffu, tm0, 1));
        tm0 = fmaxf(tm0, __shfl_xor_sync(0xffffffffu, tm0, 2));
        tm1 = fmaxf(tm1, __shfl_xor_sync(0xffffffffu, tm1, 1));
        tm1 = fmaxf(tm1, __shfl_xor_sync(0xffffffffu, tm1, 2));
        float nm0 = fmaxf(m0, tm0), nm1 = fmaxf(m1, tm1);
        float al0 = exp2f(m0 - nm0), al1 = exp2f(m1 - nm1);
        m0 = nm0; m1 = nm1;
        float ps0 = 0.f, ps1 = 0.f;
        #pragma unroll
        for (int nb = 0; nb < 8; nb++) {
            s[nb][0] = exp2f(s[nb][0] - nm0);
            s[nb][1] = exp2f(s[nb][1] - nm0);
            s[nb][2] = exp2f(s[nb][2] - nm1);
            s[nb][3] = exp2f(s[nb][3] - nm1);
            ps0 += s[nb][0] + s[nb][1];
            ps1 += s[nb][2] + s[nb][3];
        }
        ps0 += __shfl_xor_sync(0xffffffffu, ps0, 1);
        ps0 += __shfl_xor_sync(0xffffffffu, ps0, 2);
        ps1 += __shfl_xor_sync(0xffffffffu, ps1, 1);
        ps1 += __shfl_xor_sync(0xffffffffu, ps1, 2);
        l0 = l0 * al0 + ps0;
        l1 = l1 * al1 + ps1;

        #pragma unroll
        for (int nbv = 0; nbv < 4; nbv++) {
            o[nbv][0] *= al0; o[nbv][1] *= al0;
            o[nbv][2] *= al1; o[nbv][3] *= al1;
        }
        uint32_t ap[4][4];
        #pragma unroll
        for (int s4 = 0; s4 < 4; s4++) {
            ap[s4][0] = pack_bf16(s[2*s4  ][0], s[2*s4  ][1]);
            ap[s4][1] = pack_bf16(s[2*s4  ][2], s[2*s4  ][3]);
            ap[s4][2] = pack_bf16(s[2*s4+1][0], s[2*s4+1][1]);
            ap[s4][3] = pack_bf16(s[2*s4+1][2], s[2*s4+1][3]);
        }

        #pragma unroll
        for (int nbv = 0; nbv < 4; nbv++) {
            const char* vr = Vs[st] + (nbv*8 + g)*144;
            #pragma unroll
            for (int s4 = 0; s4 < 4; s4++) {
                uint32_t b0 = *(const uint32_t*)(vr + (16*s4 + 2*t)*2);
                uint32_t b1 = *(const uint32_t*)(vr + (16*s4 + 2*t + 8)*2);
                mma_bf16(o[nbv], ap[s4], b0, b1);
            }
        }
    }

    float inv0 = 1.0f / l0, inv1 = 1.0f / l1;
    int row0 = q0 + w*16 + g;
    #pragma unroll
    for (int nbv = 0; nbv < 4; nbv++) {
        int col = head*32 + nbv*8 + 2*t;
        *(float2*)(g_attn + (size_t)row0*HH + col)       = make_float2(o[nbv][0]*inv0, o[nbv][1]*inv0);
        *(float2*)(g_attn + (size_t)(row0+8)*HH + col)   = make_float2(o[nbv][2]*inv1, o[nbv][3]*inv1);
    }
}

// ---------------- output heads (warp per node) ------------------------------------
template<int C, bool SOFTMAX>
__global__ void __launch_bounds__(256) head_warp(const float* __restrict__ hid,
                                                 const float* __restrict__ W,
                                                 const float* __restrict__ b,
                                                 float* __restrict__ out) {
    const int node = blockIdx.x * 8 + (threadIdx.x >> 5);
    const int lane = threadIdx.x & 31;
    float4 hv = *(const float4*)(hid + (size_t)node*128 + lane*4);
    float lg[C];
    #pragma unroll
    for (int c = 0; c < C; c++) {
        float4 wv = *(const float4*)(W + c*128 + lane*4);
        float d = hv.x*wv.x + hv.y*wv.y + hv.z*wv.z + hv.w*wv.w;
        #pragma unroll
        for (int m = 16; m >= 1; m >>= 1) d += __shfl_xor_sync(0xffffffffu, d, m);
        lg[c] = d + b[c];
    }
    if (lane == 0) {
        if (SOFTMAX) {
            float mx = lg[0];
            #pragma unroll
            for (int c = 1; c < C; c++) mx = fmaxf(mx, lg[c]);
            float e[C]; float sum = 0.f;
            #pragma unroll
            for (int c = 0; c < C; c++) { e[c] = __expf(lg[c] - mx); sum += e[c]; }
            float inv = 1.0f / sum;
            #pragma unroll
            for (int c = 0; c < C; c++) out[(size_t)node*C + c] = e[c] * inv;
        } else {
            #pragma unroll
            for (int c = 0; c < C; c++)
                out[(size_t)node*C + c] = 1.0f / (1.0f + __expf(-lg[c]));
        }
    }
}

// ---------------- launch ---------------------------------------------------------
extern "C" void kernel_launch(void* const* d_in, const int* in_sizes, int n_in,
                              void* d_out, int out_size)
{
    const float* x     = (const float*)d_in[0];
    const int*   ei    = (const int*)  d_in[1];
    const float* W1    = (const float*)d_in[2];
    const float* b1    = (const float*)d_in[3];
    const float* W2    = (const float*)d_in[4];
    const float* b2    = (const float*)d_in[5];
    const float* W3    = (const float*)d_in[6];
    const float* b3    = (const float*)d_in[7];
    const float* in_w  = (const float*)d_in[8];
    const float* in_b  = (const float*)d_in[9];
    const float* out_w = (const float*)d_in[10];
    const float* out_b = (const float*)d_in[11];
    const float* fp1w  = (const float*)d_in[12];
    const float* fp1b  = (const float*)d_in[13];
    const float* fp2w  = (const float*)d_in[14];
    const float* fp2b  = (const float*)d_in[15];
    const float* pd1w  = (const float*)d_in[16];
    const float* pd1b  = (const float*)d_in[17];
    const float* pd2w  = (const float*)d_in[18];
    const float* pd2b  = (const float*)d_in[19];
    const int* src = ei;
    const int* dst = ei + EE;
    float* outp = (float*)d_out;

    float *tmp, *h, *h3, *deg, *attn, *hid, *hid2;
    cudaGetSymbolAddress((void**)&tmp,  g_tmp);
    cudaGetSymbolAddress((void**)&h,    g_h);
    cudaGetSymbolAddress((void**)&h3,   g_h3);
    cudaGetSymbolAddress((void**)&deg,  g_deg);
    cudaGetSymbolAddress((void**)&attn, g_attn);
    cudaGetSymbolAddress((void**)&hid,  g_hid);
    cudaGetSymbolAddress((void**)&hid2, g_hid2);

    static cudaStream_t s2 = nullptr;
    static cudaEvent_t evF = nullptr, evJ = nullptr, evF2 = nullptr, evJ2 = nullptr;
    if (!s2) {
        cudaStreamCreateWithFlags(&s2, cudaStreamNonBlocking);
        cudaEventCreateWithFlags(&evF,  cudaEventDisableTiming);
        cudaEventCreateWithFlags(&evJ,  cudaEventDisableTiming);
        cudaEventCreateWithFlags(&evF2, cudaEventDisableTiming);
        cudaEventCreateWithFlags(&evJ2, cudaEventDisableTiming);
    }

    const dim3 blk(256);

    // Fork: CSR build on s2  ||  GEMM1 on main stream
    cudaEventRecord(evF, 0);
    cudaStreamWaitEvent(s2, evF, 0);
    cudaMemsetAsync(deg, 0, NN * sizeof(float), s2);
    deg_count<<<EE/256, 256, 0, s2>>>(dst);
    scan_rowptr<<<1, 1024, 0, s2>>>();
    csr_scatter<<<EE/256, 256, 0, s2>>>(src, dst);
    cudaEventRecord(evJ, s2);

    gemm_tf32<false,false,false,false><<<dim3(4,32), blk>>>(x, W1, nullptr, nullptr, tmp, NN, HH, 128);
    cudaStreamWaitEvent(0, evJ, 0);     // join before first gather

    gcn_gather<true><<<NN/8, blk>>>(b1, h);
    gemm_tf32<false,false,false,false><<<dim3(4,32), blk>>>(h, W2, nullptr, nullptr, tmp, NN, HH, HH);
    gcn_gather<true><<<NN/8, blk>>>(b2, h);
    gemm_tf32<false,false,false,false><<<dim3(4,32), blk>>>(h, W3, nullptr, nullptr, tmp, NN, HH, HH);
    gcn_gather<false><<<NN/8, blk>>>(b3, h3);

    // MHA: fused QKV gemm -> (g_Qb, g_Kb, g_vtmp); V transpose; flash attention
    gemm_tf32<true,false,false,true><<<dim3(12,32), blk>>>(h3, in_w, in_b, nullptr, nullptr, NN, 3*HH, HH);
    v_to_bf16<<<dim3(NN/64, 8), blk>>>();
    flash_attn_bf16<<<dim3(NN/128, 8), blk>>>();
    gemm_tf32<true,false,true,false><<<dim3(4,32), blk>>>(attn, out_w, out_b, h3, h, NN, HH, HH);

    // Fork the two head chains
    cudaEventRecord(evF2, 0);
    cudaStreamWaitEvent(s2, evF2, 0);
    gemm_tf32<true,true,false,false><<<dim3(2,32), blk, 0, s2>>>(h, pd1w, pd1b, nullptr, hid2, NN, 128, HH);
    head_warp<10, false><<<NN/8, blk, 0, s2>>>(hid2, pd2w, pd2b, outp + (size_t)NN*3);
    cudaEventRecord(evJ2, s2);

    gemm_tf32<true,true,false,false><<<dim3(2,32), blk>>>(h, fp1w, fp1b, nullptr, hid, NN, 128, HH);
    head_warp<3, true><<<NN/8, blk>>>(hid, fp2w, fp2b, outp);
    cudaStreamWaitEvent(0, evJ2, 0);    // join before returning
}